// round 13
// baseline (speedup 1.0000x reference)
#include <cuda_runtime.h>
#include <cuda_fp16.h>
#include <cstdint>

#define NN   40000
#define EE   640000
#define FH   128
#define GG   256
#define NOUT 10
#define NBLK ((NN + 255) / 256)   // 157

// ---------------- scratch (static device globals; no allocs) ----------------
__device__ int   g_count[NN];
__device__ int   g_ptr[NN + 1];
__device__ int   g_cursor[NN];
__device__ float g_dinv[NN];
__device__ int   g_src[EE];
__device__ int   g_blocksum[NBLK];
__device__ float g_pool[GG * FH];
__device__ float g_buf0[(size_t)NN * FH];  // halves: [P1 | P2]
__device__ float g_buf1[(size_t)NN * FH];  // halves: [H1]

__device__ __forceinline__ uint32_t h2u(__half2 h) { return *reinterpret_cast<uint32_t*>(&h); }
__device__ __forceinline__ __half2  u2h(uint32_t u) { return *reinterpret_cast<__half2*>(&u); }

// ---------------- CSR build (R11-frozen 3-stage scan) ----------------
// 4 edges per thread via int4
__global__ void __launch_bounds__(256) k_hist(const int* __restrict__ ei) {
    int e4 = (blockIdx.x * blockDim.x + threadIdx.x) * 4;
    if (e4 < EE) {
        int4 c = *(const int4*)(ei + EE + e4);
        atomicAdd(&g_count[c.x], 1);
        atomicAdd(&g_count[c.y], 1);
        atomicAdd(&g_count[c.z], 1);
        atomicAdd(&g_count[c.w], 1);
    }
}

__global__ void __launch_bounds__(256) k_block_reduce() {
    __shared__ int ws[8];
    int i = blockIdx.x * 256 + threadIdx.x;
    int v = (i < NN) ? g_count[i] : 0;
#pragma unroll
    for (int o = 16; o > 0; o >>= 1) v += __shfl_down_sync(0xffffffffu, v, o);
    if ((threadIdx.x & 31) == 0) ws[threadIdx.x >> 5] = v;
    __syncthreads();
    if (threadIdx.x < 8) {
        int s = ws[threadIdx.x];
#pragma unroll
        for (int o = 4; o > 0; o >>= 1) s += __shfl_down_sync(0xffu, s, o);
        if (threadIdx.x == 0) g_blocksum[blockIdx.x] = s;
    }
}

__global__ void __launch_bounds__(256) k_block_offsets() {
    __shared__ int sm[256];
    int t = threadIdx.x;
    int v = (t < NBLK) ? g_blocksum[t] : 0;
    sm[t] = v;
    __syncthreads();
    for (int off = 1; off < 256; off <<= 1) {
        int u = (t >= off) ? sm[t - off] : 0;
        __syncthreads();
        sm[t] += u;
        __syncthreads();
    }
    if (t < NBLK) g_blocksum[t] = sm[t] - v;  // exclusive
}

__global__ void __launch_bounds__(256) k_ptr_dinv() {
    __shared__ int ws[8];
    int t = threadIdx.x;
    int i = blockIdx.x * 256 + t;
    int c = (i < NN) ? g_count[i] : 0;
    int lane = t & 31, warp = t >> 5;

    int inc = c;
#pragma unroll
    for (int o = 1; o < 32; o <<= 1) {
        int u = __shfl_up_sync(0xffffffffu, inc, o);
        if (lane >= o) inc += u;
    }
    if (lane == 31) ws[warp] = inc;
    __syncthreads();
    if (t < 8) {
        int s = ws[t];
#pragma unroll
        for (int o = 1; o < 8; o <<= 1) {
            int u = __shfl_up_sync(0xffu, s, o);
            if (t >= o) s += u;
        }
        ws[t] = s;
    }
    __syncthreads();
    int ex = inc - c + (warp ? ws[warp - 1] : 0);

    if (i < NN) {
        int p = g_blocksum[blockIdx.x] + ex;
        g_ptr[i]    = p;
        g_cursor[i] = p;
        g_dinv[i]   = rsqrtf((float)(c + 1));
        if (i == NN - 1) g_ptr[NN] = p + c;
    }
}

// 4 edges per thread via int4
__global__ void __launch_bounds__(256) k_scatter(const int* __restrict__ ei) {
    int e4 = (blockIdx.x * blockDim.x + threadIdx.x) * 4;
    if (e4 < EE) {
        int4 r = *(const int4*)(ei + e4);
        int4 c = *(const int4*)(ei + EE + e4);
        int p0 = atomicAdd(&g_cursor[c.x], 1);
        int p1 = atomicAdd(&g_cursor[c.y], 1);
        int p2 = atomicAdd(&g_cursor[c.z], 1);
        int p3 = atomicAdd(&g_cursor[c.w], 1);
        g_src[p0] = r.x;
        g_src[p1] = r.y;
        g_src[p2] = r.z;
        g_src[p3] = r.w;
    }
}

// ---------------- fp16 mma GEMM: C[rows,128](fp16) = [row_scale .*] (A @ W) ----------------
#define AHS 136
#define BHS 136
#define SMEM_GEMM ((128 * AHS + 128 * BHS) * 2)

__device__ __forceinline__ void mma_f16(float* c, uint32_t a0, uint32_t a1, uint32_t a2,
                                        uint32_t a3, uint32_t b0, uint32_t b1) {
    asm volatile(
        "mma.sync.aligned.m16n8k16.row.col.f32.f16.f16.f32 "
        "{%0,%1,%2,%3}, {%4,%5,%6,%7}, {%8,%9}, {%0,%1,%2,%3};"
        : "+f"(c[0]), "+f"(c[1]), "+f"(c[2]), "+f"(c[3])
        : "r"(a0), "r"(a1), "r"(a2), "r"(a3), "r"(b0), "r"(b1));
}

__global__ void __launch_bounds__(256, 2) k_gemm_h(
    const void* __restrict__ Ain, int a_fp32,
    const float* __restrict__ W, __half* __restrict__ C,
    const float* __restrict__ row_scale, int M) {
    extern __shared__ __half sh[];
    __half* As = sh;
    __half* Bs = sh + 128 * AHS;
    int tid = threadIdx.x;
    int row0 = blockIdx.x * 128;

    if (a_fp32) {
        const float* A = (const float*)Ain;
        for (int i = tid; i < 4096; i += 256) {
            int r = i >> 5, c = (i & 31) << 2;
            int gr = row0 + r;
            float4 v = make_float4(0.f, 0.f, 0.f, 0.f);
            if (gr < M) v = *(const float4*)(A + (size_t)gr * 128 + c);
            uint2 u;
            u.x = h2u(__floats2half2_rn(v.x, v.y));
            u.y = h2u(__floats2half2_rn(v.z, v.w));
            *(uint2*)(As + r * AHS + c) = u;
        }
    } else {
        const __half* A = (const __half*)Ain;
        for (int i = tid; i < 4096; i += 256) {
            int r = i >> 5, c = (i & 31) << 2;
            int gr = row0 + r;
            uint2 u = make_uint2(0u, 0u);
            if (gr < M) u = *(const uint2*)(A + (size_t)gr * 128 + c);
            *(uint2*)(As + r * AHS + c) = u;
        }
    }

    for (int t = 0; t < 8; t++) {
        int idx = tid + t * 256;
        int k2 = (idx & 31) | (((idx >> 5) & 1) << 5);
        int n4 = (idx >> 6) << 2;
        int k = k2 * 2;
        const float* w0 = W + (size_t)k * 128 + n4;
        float4 r0 = *(const float4*)w0;
        float4 r1 = *(const float4*)(w0 + 128);
        *(uint32_t*)(Bs + (n4 + 0) * BHS + k) = h2u(__floats2half2_rn(r0.x, r1.x));
        *(uint32_t*)(Bs + (n4 + 1) * BHS + k) = h2u(__floats2half2_rn(r0.y, r1.y));
        *(uint32_t*)(Bs + (n4 + 2) * BHS + k) = h2u(__floats2half2_rn(r0.z, r1.z));
        *(uint32_t*)(Bs + (n4 + 3) * BHS + k) = h2u(__floats2half2_rn(r0.w, r1.w));
    }
    __syncthreads();

    int wid = tid >> 5, lane = tid & 31;
    int wm = (wid >> 2) * 64;
    int wn = (wid & 3) * 32;
    int g = lane >> 2, tg = lane & 3;

    float acc[4][4][4];
#pragma unroll
    for (int mt = 0; mt < 4; mt++)
#pragma unroll
        for (int nt = 0; nt < 4; nt++)
#pragma unroll
            for (int r = 0; r < 4; r++) acc[mt][nt][r] = 0.f;

#pragma unroll
    for (int k0 = 0; k0 < 128; k0 += 16) {
        uint32_t af[4][4];
#pragma unroll
        for (int mt = 0; mt < 4; mt++) {
            const __half* ap = As + (wm + mt * 16) * AHS + k0 + tg * 2;
            af[mt][0] = *(const uint32_t*)(ap + g * AHS);
            af[mt][1] = *(const uint32_t*)(ap + (g + 8) * AHS);
            af[mt][2] = *(const uint32_t*)(ap + g * AHS + 8);
            af[mt][3] = *(const uint32_t*)(ap + (g + 8) * AHS + 8);
        }
        uint32_t bf[4][2];
#pragma unroll
        for (int nt = 0; nt < 4; nt++) {
            const __half* bp = Bs + (wn + nt * 8 + g) * BHS + k0 + tg * 2;
            bf[nt][0] = *(const uint32_t*)(bp);
            bf[nt][1] = *(const uint32_t*)(bp + 8);
        }
#pragma unroll
        for (int mt = 0; mt < 4; mt++)
#pragma unroll
            for (int nt = 0; nt < 4; nt++)
                mma_f16(acc[mt][nt], af[mt][0], af[mt][1], af[mt][2], af[mt][3],
                        bf[nt][0], bf[nt][1]);
    }

#pragma unroll
    for (int nt = 0; nt < 4; nt++) {
        int col = wn + nt * 8 + tg * 2;
#pragma unroll
        for (int mt = 0; mt < 4; mt++) {
            int r0 = row0 + wm + mt * 16 + g;
            if (r0 < M) {
                float s0 = row_scale ? row_scale[r0] : 1.0f;
                *(uint32_t*)(C + (size_t)r0 * 128 + col) =
                    h2u(__floats2half2_rn(acc[mt][nt][0] * s0, acc[mt][nt][1] * s0));
            }
            int r1 = r0 + 8;
            if (r1 < M) {
                float s1 = row_scale ? row_scale[r1] : 1.0f;
                *(uint32_t*)(C + (size_t)r1 * 128 + col) =
                    h2u(__floats2half2_rn(acc[mt][nt][2] * s1, acc[mt][nt][3] * s1));
            }
        }
    }
}

// ---------------- agg core: returns the 4 output floats for (node, lane) ----------------
template <int PRESCALED>
__device__ __forceinline__ void agg_row(
    const __half* __restrict__ P, const float* __restrict__ bias,
    int node, int lane, float& ox, float& oy, float& oz, float& ow) {
    int c4 = lane * 4;
    float di = g_dinv[node];

    uint2 sv = *(const uint2*)(P + (size_t)node * FH + c4);
    float2 f0 = __half22float2(u2h(sv.x));
    float2 f1 = __half22float2(u2h(sv.y));
    float selfs = PRESCALED ? 1.0f : di;
    float ax = selfs * f0.x, ay = selfs * f0.y, az = selfs * f1.x, aw = selfs * f1.y;

    int beg = g_ptr[node], end = g_ptr[node + 1];
    int j = beg;
    for (; j + 8 <= end; j += 8) {
        int s[8];
#pragma unroll
        for (int q = 0; q < 8; q++) s[q] = g_src[j + q];
        float d[8];
#pragma unroll
        for (int q = 0; q < 8; q++) d[q] = PRESCALED ? 1.0f : g_dinv[s[q]];
        uint2 v[8];
#pragma unroll
        for (int q = 0; q < 8; q++) v[q] = *(const uint2*)(P + (size_t)s[q] * FH + c4);
#pragma unroll
        for (int q = 0; q < 8; q++) {
            float2 a = __half22float2(u2h(v[q].x));
            float2 b = __half22float2(u2h(v[q].y));
            if (PRESCALED) {
                ax += a.x; ay += a.y; az += b.x; aw += b.y;
            } else {
                ax = fmaf(d[q], a.x, ax); ay = fmaf(d[q], a.y, ay);
                az = fmaf(d[q], b.x, az); aw = fmaf(d[q], b.y, aw);
            }
        }
    }
    for (; j + 4 <= end; j += 4) {
        int s[4];
#pragma unroll
        for (int q = 0; q < 4; q++) s[q] = g_src[j + q];
        float d[4];
#pragma unroll
        for (int q = 0; q < 4; q++) d[q] = PRESCALED ? 1.0f : g_dinv[s[q]];
        uint2 v[4];
#pragma unroll
        for (int q = 0; q < 4; q++) v[q] = *(const uint2*)(P + (size_t)s[q] * FH + c4);
#pragma unroll
        for (int q = 0; q < 4; q++) {
            float2 a = __half22float2(u2h(v[q].x));
            float2 b = __half22float2(u2h(v[q].y));
            if (PRESCALED) {
                ax += a.x; ay += a.y; az += b.x; aw += b.y;
            } else {
                ax = fmaf(d[q], a.x, ax); ay = fmaf(d[q], a.y, ay);
                az = fmaf(d[q], b.x, az); aw = fmaf(d[q], b.y, aw);
            }
        }
    }
    for (; j < end; j++) {
        int s0 = g_src[j];
        float d0 = PRESCALED ? 1.0f : g_dinv[s0];
        uint2 v0 = *(const uint2*)(P + (size_t)s0 * FH + c4);
        float2 a0 = __half22float2(u2h(v0.x)), b0 = __half22float2(u2h(v0.y));
        ax = fmaf(d0, a0.x, ax); ay = fmaf(d0, a0.y, ay);
        az = fmaf(d0, b0.x, az); aw = fmaf(d0, b0.y, aw);
    }

    float4 bb = *(const float4*)(bias + c4);
    ox = fmaxf(fmaf(ax, di, bb.x), 0.f);
    oy = fmaxf(fmaf(ay, di, bb.y), 0.f);
    oz = fmaxf(fmaf(az, di, bb.z), 0.f);
    ow = fmaxf(fmaf(aw, di, bb.w), 0.f);
}

// layer-1 agg: h1 -> fp16 buffer
__global__ void __launch_bounds__(256) k_agg_h1(
    const __half* __restrict__ P, __half* __restrict__ Hout,
    const float* __restrict__ bias) {
    int node = (blockIdx.x * blockDim.x + threadIdx.x) >> 5;
    int lane = threadIdx.x & 31;
    if (node >= NN) return;
    float ox, oy, oz, ow;
    agg_row<0>(P, bias, node, lane, ox, oy, oz, ow);
    uint2 o;
    o.x = h2u(__floats2half2_rn(ox, oy));
    o.y = h2u(__floats2half2_rn(oz, ow));
    *(uint2*)(Hout + (size_t)node * FH + lane * 4) = o;
}

// layer-2 agg fused with mean-pool accumulation (h2 never materialized)
__global__ void __launch_bounds__(256) k_agg_pool(
    const __half* __restrict__ P, const float* __restrict__ bias,
    const int* __restrict__ batch) {
    int node = (blockIdx.x * blockDim.x + threadIdx.x) >> 5;
    int lane = threadIdx.x & 31;
    if (node >= NN) return;
    float ox, oy, oz, ow;
    agg_row<1>(P, bias, node, lane, ox, oy, oz, ow);
    int gid = batch[node];  // same address across warp -> broadcast
    float* dst = g_pool + gid * FH + lane * 4;
    atomicAdd(dst + 0, ox);
    atomicAdd(dst + 1, oy);
    atomicAdd(dst + 2, oz);
    atomicAdd(dst + 3, ow);
}

// ---------------- FC + log_softmax over pooled sums ----------------
__device__ __forceinline__ int lower_bound_i(const int* __restrict__ b, int n, int key) {
    int lo = 0, hi = n;
    while (lo < hi) {
        int mid = (lo + hi) >> 1;
        if (b[mid] < key) lo = mid + 1; else hi = mid;
    }
    return lo;
}

__global__ void __launch_bounds__(128) k_fc(
    const int* __restrict__ batch,
    const float* __restrict__ Wfc, const float* __restrict__ bfc,
    float* __restrict__ out) {
    int g = blockIdx.x;
    int tid = threadIdx.x;
    __shared__ float pooled[FH];
    __shared__ float logit[NOUT];
    __shared__ int range[2];

    if (tid == 0) {
        range[0] = lower_bound_i(batch, NN, g);
        range[1] = lower_bound_i(batch, NN, g + 1);
    }
    __syncthreads();
    float cnt = fmaxf((float)(range[1] - range[0]), 1.0f);
    pooled[tid] = g_pool[g * FH + tid] / cnt;
    __syncthreads();

    if (tid < NOUT) {
        float acc = bfc[tid];
        for (int k = 0; k < FH; k++) acc = fmaf(pooled[k], Wfc[k * NOUT + tid], acc);
        logit[tid] = acc;
    }
    __syncthreads();

    if (tid == 0) {
        float m = -1e30f;
        for (int o = 0; o < NOUT; o++) m = fmaxf(m, logit[o]);
        float se = 0.f;
        for (int o = 0; o < NOUT; o++) se += expf(logit[o] - m);
        float lse = m + logf(se);
        for (int o = 0; o < NOUT; o++) out[g * NOUT + o] = logit[o] - lse;
    }
}

// ---------------- launch (R8/R11 schedule, verified optimum) ----------------
struct HxRes {
    cudaStream_t s2;
    cudaEvent_t e0, e1;
    HxRes() {
        cudaStreamCreateWithFlags(&s2, cudaStreamNonBlocking);
        cudaEventCreateWithFlags(&e0, cudaEventDisableTiming);
        cudaEventCreateWithFlags(&e1, cudaEventDisableTiming);
    }
};

extern "C" void kernel_launch(void* const* d_in, const int* in_sizes, int n_in,
                              void* d_out, int out_size) {
    static HxRes hx;

    const float* x    = (const float*)d_in[0];
    const int*   ei   = (const int*)d_in[1];
    const int*   batc = (const int*)d_in[2];
    const float* W1   = (const float*)d_in[3];
    const float* b1   = (const float*)d_in[4];
    const float* W2   = (const float*)d_in[5];
    const float* b2   = (const float*)d_in[6];
    const float* Wfc  = (const float*)d_in[7];
    const float* bfc  = (const float*)d_in[8];
    float* out = (float*)d_out;

    void *p0, *p1, *pc, *pp;
    cudaGetSymbolAddress(&p0, g_buf0);
    cudaGetSymbolAddress(&p1, g_buf1);
    cudaGetSymbolAddress(&pc, g_count);
    cudaGetSymbolAddress(&pp, g_pool);
    __half* bufP1 = (__half*)p0;                     // P1 = X @ W1
    __half* bufP2 = (__half*)p0 + (size_t)NN * FH;   // P2 = dinv .* (H1 @ W2)
    __half* bufH  = (__half*)p1;                     // H1

    float* dinv_ptr;
    cudaGetSymbolAddress((void**)&dinv_ptr, g_dinv);

    cudaFuncSetAttribute(k_gemm_h,
                         cudaFuncAttributeMaxDynamicSharedMemorySize, SMEM_GEMM);

    int gblocks = (NN + 127) / 128;

    // fork: GEMM1 (P1 = X @ W1) at t=0, concurrent with the whole CSR build
    cudaEventRecord(hx.e0, 0);
    cudaStreamWaitEvent(hx.s2, hx.e0, 0);
    k_gemm_h<<<gblocks, 256, SMEM_GEMM, hx.s2>>>(x, 1, W1, bufP1, nullptr, NN);
    cudaEventRecord(hx.e1, hx.s2);

    // CSR build on the main (capturing) stream — memset + 3-stage scan (frozen)
    cudaMemsetAsync(pc, 0, NN * sizeof(int), 0);
    cudaMemsetAsync(pp, 0, GG * FH * sizeof(float), 0);
    k_hist<<<(EE / 4 + 255) / 256, 256>>>(ei);
    k_block_reduce<<<NBLK, 256>>>();
    k_block_offsets<<<1, 256>>>();
    k_ptr_dinv<<<NBLK, 256>>>();
    k_scatter<<<(EE / 4 + 255) / 256, 256>>>(ei);

    // join GEMM1, then h1 = relu(agg(P1) + b1)  (dinv gathered per edge)
    cudaStreamWaitEvent(0, hx.e1, 0);
    k_agg_h1<<<NN / 8, 256>>>(bufP1, bufH, b1);

    // layer 2: P2 = dinv .* (H1 @ W2); agg2 fused with pooled accumulation
    k_gemm_h<<<gblocks, 256, SMEM_GEMM>>>(bufH, 0, W2, bufP2, dinv_ptr, NN);
    k_agg_pool<<<NN / 8, 256>>>(bufP2, b2, batc);

    // FC + log_softmax over pooled sums
    k_fc<<<GG, 128>>>(batc, Wfc, bfc, out);
}

// round 14
// speedup vs baseline: 1.2033x; 1.2033x over previous
#include <cuda_runtime.h>
#include <cuda_fp16.h>
#include <cstdint>

#define NN   40000
#define EE   640000
#define FH   128
#define GG   256
#define NOUT 10
#define NBLK ((NN + 255) / 256)   // 157

// ---------------- scratch (static device globals; no allocs) ----------------
__device__ int   g_count[NN];
__device__ int   g_ptr[NN + 1];
__device__ int   g_cursor[NN];
__device__ float g_dinv[NN];
__device__ int   g_src[EE];
__device__ int   g_blocksum[NBLK];
__device__ float g_buf0[(size_t)NN * FH];  // halves: [P1 | P2]
__device__ float g_buf1[(size_t)NN * FH];  // halves: [H1, then H2]

__device__ __forceinline__ uint32_t h2u(__half2 h) { return *reinterpret_cast<uint32_t*>(&h); }
__device__ __forceinline__ __half2  u2h(uint32_t u) { return *reinterpret_cast<__half2*>(&u); }

// ---------------- CSR build (R11-frozen 3-stage scan) ----------------
// 4 edges per thread via int4
__global__ void __launch_bounds__(256) k_hist(const int* __restrict__ ei) {
    int e4 = (blockIdx.x * blockDim.x + threadIdx.x) * 4;
    if (e4 < EE) {
        int4 c = *(const int4*)(ei + EE + e4);
        atomicAdd(&g_count[c.x], 1);
        atomicAdd(&g_count[c.y], 1);
        atomicAdd(&g_count[c.z], 1);
        atomicAdd(&g_count[c.w], 1);
    }
}

__global__ void __launch_bounds__(256) k_block_reduce() {
    __shared__ int ws[8];
    int i = blockIdx.x * 256 + threadIdx.x;
    int v = (i < NN) ? g_count[i] : 0;
#pragma unroll
    for (int o = 16; o > 0; o >>= 1) v += __shfl_down_sync(0xffffffffu, v, o);
    if ((threadIdx.x & 31) == 0) ws[threadIdx.x >> 5] = v;
    __syncthreads();
    if (threadIdx.x < 8) {
        int s = ws[threadIdx.x];
#pragma unroll
        for (int o = 4; o > 0; o >>= 1) s += __shfl_down_sync(0xffu, s, o);
        if (threadIdx.x == 0) g_blocksum[blockIdx.x] = s;
    }
}

__global__ void __launch_bounds__(256) k_block_offsets() {
    __shared__ int sm[256];
    int t = threadIdx.x;
    int v = (t < NBLK) ? g_blocksum[t] : 0;
    sm[t] = v;
    __syncthreads();
    for (int off = 1; off < 256; off <<= 1) {
        int u = (t >= off) ? sm[t - off] : 0;
        __syncthreads();
        sm[t] += u;
        __syncthreads();
    }
    if (t < NBLK) g_blocksum[t] = sm[t] - v;  // exclusive
}

__global__ void __launch_bounds__(256) k_ptr_dinv() {
    __shared__ int ws[8];
    int t = threadIdx.x;
    int i = blockIdx.x * 256 + t;
    int c = (i < NN) ? g_count[i] : 0;
    int lane = t & 31, warp = t >> 5;

    int inc = c;
#pragma unroll
    for (int o = 1; o < 32; o <<= 1) {
        int u = __shfl_up_sync(0xffffffffu, inc, o);
        if (lane >= o) inc += u;
    }
    if (lane == 31) ws[warp] = inc;
    __syncthreads();
    if (t < 8) {
        int s = ws[t];
#pragma unroll
        for (int o = 1; o < 8; o <<= 1) {
            int u = __shfl_up_sync(0xffu, s, o);
            if (t >= o) s += u;
        }
        ws[t] = s;
    }
    __syncthreads();
    int ex = inc - c + (warp ? ws[warp - 1] : 0);

    if (i < NN) {
        int p = g_blocksum[blockIdx.x] + ex;
        g_ptr[i]    = p;
        g_cursor[i] = p;
        g_dinv[i]   = rsqrtf((float)(c + 1));
        if (i == NN - 1) g_ptr[NN] = p + c;
    }
}

// 4 edges per thread via int4
__global__ void __launch_bounds__(256) k_scatter(const int* __restrict__ ei) {
    int e4 = (blockIdx.x * blockDim.x + threadIdx.x) * 4;
    if (e4 < EE) {
        int4 r = *(const int4*)(ei + e4);
        int4 c = *(const int4*)(ei + EE + e4);
        int p0 = atomicAdd(&g_cursor[c.x], 1);
        int p1 = atomicAdd(&g_cursor[c.y], 1);
        int p2 = atomicAdd(&g_cursor[c.z], 1);
        int p3 = atomicAdd(&g_cursor[c.w], 1);
        g_src[p0] = r.x;
        g_src[p1] = r.y;
        g_src[p2] = r.z;
        g_src[p3] = r.w;
    }
}

// ---------------- fp16 mma GEMM: C[rows,128](fp16) = [row_scale .*] (A @ W) ----------------
#define AHS 136
#define BHS 136
#define SMEM_GEMM ((128 * AHS + 128 * BHS) * 2)

__device__ __forceinline__ void mma_f16(float* c, uint32_t a0, uint32_t a1, uint32_t a2,
                                        uint32_t a3, uint32_t b0, uint32_t b1) {
    asm volatile(
        "mma.sync.aligned.m16n8k16.row.col.f32.f16.f16.f32 "
        "{%0,%1,%2,%3}, {%4,%5,%6,%7}, {%8,%9}, {%0,%1,%2,%3};"
        : "+f"(c[0]), "+f"(c[1]), "+f"(c[2]), "+f"(c[3])
        : "r"(a0), "r"(a1), "r"(a2), "r"(a3), "r"(b0), "r"(b1));
}

__global__ void __launch_bounds__(256, 2) k_gemm_h(
    const void* __restrict__ Ain, int a_fp32,
    const float* __restrict__ W, __half* __restrict__ C,
    const float* __restrict__ row_scale, int M) {
    extern __shared__ __half sh[];
    __half* As = sh;
    __half* Bs = sh + 128 * AHS;
    int tid = threadIdx.x;
    int row0 = blockIdx.x * 128;

    if (a_fp32) {
        const float* A = (const float*)Ain;
        for (int i = tid; i < 4096; i += 256) {
            int r = i >> 5, c = (i & 31) << 2;
            int gr = row0 + r;
            float4 v = make_float4(0.f, 0.f, 0.f, 0.f);
            if (gr < M) v = *(const float4*)(A + (size_t)gr * 128 + c);
            uint2 u;
            u.x = h2u(__floats2half2_rn(v.x, v.y));
            u.y = h2u(__floats2half2_rn(v.z, v.w));
            *(uint2*)(As + r * AHS + c) = u;
        }
    } else {
        const __half* A = (const __half*)Ain;
        for (int i = tid; i < 4096; i += 256) {
            int r = i >> 5, c = (i & 31) << 2;
            int gr = row0 + r;
            uint2 u = make_uint2(0u, 0u);
            if (gr < M) u = *(const uint2*)(A + (size_t)gr * 128 + c);
            *(uint2*)(As + r * AHS + c) = u;
        }
    }

    for (int t = 0; t < 8; t++) {
        int idx = tid + t * 256;
        int k2 = (idx & 31) | (((idx >> 5) & 1) << 5);
        int n4 = (idx >> 6) << 2;
        int k = k2 * 2;
        const float* w0 = W + (size_t)k * 128 + n4;
        float4 r0 = *(const float4*)w0;
        float4 r1 = *(const float4*)(w0 + 128);
        *(uint32_t*)(Bs + (n4 + 0) * BHS + k) = h2u(__floats2half2_rn(r0.x, r1.x));
        *(uint32_t*)(Bs + (n4 + 1) * BHS + k) = h2u(__floats2half2_rn(r0.y, r1.y));
        *(uint32_t*)(Bs + (n4 + 2) * BHS + k) = h2u(__floats2half2_rn(r0.z, r1.z));
        *(uint32_t*)(Bs + (n4 + 3) * BHS + k) = h2u(__floats2half2_rn(r0.w, r1.w));
    }
    __syncthreads();

    int wid = tid >> 5, lane = tid & 31;
    int wm = (wid >> 2) * 64;
    int wn = (wid & 3) * 32;
    int g = lane >> 2, tg = lane & 3;

    float acc[4][4][4];
#pragma unroll
    for (int mt = 0; mt < 4; mt++)
#pragma unroll
        for (int nt = 0; nt < 4; nt++)
#pragma unroll
            for (int r = 0; r < 4; r++) acc[mt][nt][r] = 0.f;

#pragma unroll
    for (int k0 = 0; k0 < 128; k0 += 16) {
        uint32_t af[4][4];
#pragma unroll
        for (int mt = 0; mt < 4; mt++) {
            const __half* ap = As + (wm + mt * 16) * AHS + k0 + tg * 2;
            af[mt][0] = *(const uint32_t*)(ap + g * AHS);
            af[mt][1] = *(const uint32_t*)(ap + (g + 8) * AHS);
            af[mt][2] = *(const uint32_t*)(ap + g * AHS + 8);
            af[mt][3] = *(const uint32_t*)(ap + (g + 8) * AHS + 8);
        }
        uint32_t bf[4][2];
#pragma unroll
        for (int nt = 0; nt < 4; nt++) {
            const __half* bp = Bs + (wn + nt * 8 + g) * BHS + k0 + tg * 2;
            bf[nt][0] = *(const uint32_t*)(bp);
            bf[nt][1] = *(const uint32_t*)(bp + 8);
        }
#pragma unroll
        for (int mt = 0; mt < 4; mt++)
#pragma unroll
            for (int nt = 0; nt < 4; nt++)
                mma_f16(acc[mt][nt], af[mt][0], af[mt][1], af[mt][2], af[mt][3],
                        bf[nt][0], bf[nt][1]);
    }

#pragma unroll
    for (int nt = 0; nt < 4; nt++) {
        int col = wn + nt * 8 + tg * 2;
#pragma unroll
        for (int mt = 0; mt < 4; mt++) {
            int r0 = row0 + wm + mt * 16 + g;
            if (r0 < M) {
                float s0 = row_scale ? row_scale[r0] : 1.0f;
                *(uint32_t*)(C + (size_t)r0 * 128 + col) =
                    h2u(__floats2half2_rn(acc[mt][nt][0] * s0, acc[mt][nt][1] * s0));
            }
            int r1 = r0 + 8;
            if (r1 < M) {
                float s1 = row_scale ? row_scale[r1] : 1.0f;
                *(uint32_t*)(C + (size_t)r1 * 128 + col) =
                    h2u(__floats2half2_rn(acc[mt][nt][2] * s1, acc[mt][nt][3] * s1));
            }
        }
    }
}

// ---------------- fp16 aggregation + bias + relu (8-wide MLP inner loop) ----------------
// PRESCALED=0: Hout[i] = relu(di*(di*P[i] + sum_s dinv[s]*P[s]) + b)
// PRESCALED=1: rows of P prescaled by dinv -> Hout[i] = relu(di*(P[i] + sum_s P[s]) + b)
template <int PRESCALED>
__global__ void __launch_bounds__(256) k_agg_h(
    const __half* __restrict__ P, __half* __restrict__ Hout,
    const float* __restrict__ bias) {
    int node = (blockIdx.x * blockDim.x + threadIdx.x) >> 5;
    int lane = threadIdx.x & 31;
    if (node >= NN) return;
    int c4 = lane * 4;
    float di = g_dinv[node];

    uint2 sv = *(const uint2*)(P + (size_t)node * FH + c4);
    float2 f0 = __half22float2(u2h(sv.x));
    float2 f1 = __half22float2(u2h(sv.y));
    float selfs = PRESCALED ? 1.0f : di;
    float ax = selfs * f0.x, ay = selfs * f0.y, az = selfs * f1.x, aw = selfs * f1.y;

    int beg = g_ptr[node], end = g_ptr[node + 1];
    int j = beg;

    for (; j + 8 <= end; j += 8) {
        int s[8];
#pragma unroll
        for (int q = 0; q < 8; q++) s[q] = g_src[j + q];
        float d[8];
#pragma unroll
        for (int q = 0; q < 8; q++) d[q] = PRESCALED ? 1.0f : g_dinv[s[q]];
        uint2 v[8];
#pragma unroll
        for (int q = 0; q < 8; q++) v[q] = *(const uint2*)(P + (size_t)s[q] * FH + c4);
#pragma unroll
        for (int q = 0; q < 8; q++) {
            float2 a = __half22float2(u2h(v[q].x));
            float2 b = __half22float2(u2h(v[q].y));
            if (PRESCALED) {
                ax += a.x; ay += a.y; az += b.x; aw += b.y;
            } else {
                ax = fmaf(d[q], a.x, ax); ay = fmaf(d[q], a.y, ay);
                az = fmaf(d[q], b.x, az); aw = fmaf(d[q], b.y, aw);
            }
        }
    }
    for (; j + 4 <= end; j += 4) {
        int s[4];
#pragma unroll
        for (int q = 0; q < 4; q++) s[q] = g_src[j + q];
        float d[4];
#pragma unroll
        for (int q = 0; q < 4; q++) d[q] = PRESCALED ? 1.0f : g_dinv[s[q]];
        uint2 v[4];
#pragma unroll
        for (int q = 0; q < 4; q++) v[q] = *(const uint2*)(P + (size_t)s[q] * FH + c4);
#pragma unroll
        for (int q = 0; q < 4; q++) {
            float2 a = __half22float2(u2h(v[q].x));
            float2 b = __half22float2(u2h(v[q].y));
            if (PRESCALED) {
                ax += a.x; ay += a.y; az += b.x; aw += b.y;
            } else {
                ax = fmaf(d[q], a.x, ax); ay = fmaf(d[q], a.y, ay);
                az = fmaf(d[q], b.x, az); aw = fmaf(d[q], b.y, aw);
            }
        }
    }
    for (; j < end; j++) {
        int s0 = g_src[j];
        float d0 = PRESCALED ? 1.0f : g_dinv[s0];
        uint2 v0 = *(const uint2*)(P + (size_t)s0 * FH + c4);
        float2 a0 = __half22float2(u2h(v0.x)), b0 = __half22float2(u2h(v0.y));
        ax = fmaf(d0, a0.x, ax); ay = fmaf(d0, a0.y, ay);
        az = fmaf(d0, b0.x, az); aw = fmaf(d0, b0.y, aw);
    }

    float4 bb = *(const float4*)(bias + c4);
    float ox = fmaxf(fmaf(ax, di, bb.x), 0.f);
    float oy = fmaxf(fmaf(ay, di, bb.y), 0.f);
    float oz = fmaxf(fmaf(az, di, bb.z), 0.f);
    float ow = fmaxf(fmaf(aw, di, bb.w), 0.f);
    uint2 o;
    o.x = h2u(__floats2half2_rn(ox, oy));
    o.y = h2u(__floats2half2_rn(oz, ow));
    *(uint2*)(Hout + (size_t)node * FH + c4) = o;
}

// ---------------- mean pool (batch sorted) + FC + log_softmax ----------------
__device__ __forceinline__ int lower_bound_i(const int* __restrict__ b, int n, int key) {
    int lo = 0, hi = n;
    while (lo < hi) {
        int mid = (lo + hi) >> 1;
        if (b[mid] < key) lo = mid + 1; else hi = mid;
    }
    return lo;
}

__global__ void __launch_bounds__(128) k_pool_fc(
    const __half* __restrict__ H2, const int* __restrict__ batch,
    const float* __restrict__ Wfc, const float* __restrict__ bfc,
    float* __restrict__ out) {
    int g = blockIdx.x;
    int tid = threadIdx.x;
    __shared__ float pooled[FH];
    __shared__ float logit[NOUT];
    __shared__ int range[2];

    if (tid == 0) {
        range[0] = lower_bound_i(batch, NN, g);
        range[1] = lower_bound_i(batch, NN, g + 1);
    }
    __syncthreads();
    int lo = range[0], hi = range[1];

    float s = 0.f;
    for (int n = lo; n < hi; n++) s += __half2float(H2[(size_t)n * FH + tid]);
    pooled[tid] = s / fmaxf((float)(hi - lo), 1.0f);
    __syncthreads();

    if (tid < NOUT) {
        float acc = bfc[tid];
        for (int k = 0; k < FH; k++) acc = fmaf(pooled[k], Wfc[k * NOUT + tid], acc);
        logit[tid] = acc;
    }
    __syncthreads();

    if (tid == 0) {
        float m = -1e30f;
        for (int o = 0; o < NOUT; o++) m = fmaxf(m, logit[o]);
        float se = 0.f;
        for (int o = 0; o < NOUT; o++) se += expf(logit[o] - m);
        float lse = m + logf(se);
        for (int o = 0; o < NOUT; o++) out[g * NOUT + o] = logit[o] - lse;
    }
}

// ---------------- launch (R8/R11 schedule, verified optimum) ----------------
struct HxRes {
    cudaStream_t s2;
    cudaEvent_t e0, e1;
    HxRes() {
        cudaStreamCreateWithFlags(&s2, cudaStreamNonBlocking);
        cudaEventCreateWithFlags(&e0, cudaEventDisableTiming);
        cudaEventCreateWithFlags(&e1, cudaEventDisableTiming);
    }
};

extern "C" void kernel_launch(void* const* d_in, const int* in_sizes, int n_in,
                              void* d_out, int out_size) {
    static HxRes hx;

    const float* x    = (const float*)d_in[0];
    const int*   ei   = (const int*)d_in[1];
    const int*   batc = (const int*)d_in[2];
    const float* W1   = (const float*)d_in[3];
    const float* b1   = (const float*)d_in[4];
    const float* W2   = (const float*)d_in[5];
    const float* b2   = (const float*)d_in[6];
    const float* Wfc  = (const float*)d_in[7];
    const float* bfc  = (const float*)d_in[8];
    float* out = (float*)d_out;

    void *p0, *p1, *pc;
    cudaGetSymbolAddress(&p0, g_buf0);
    cudaGetSymbolAddress(&p1, g_buf1);
    cudaGetSymbolAddress(&pc, g_count);
    __half* bufP1 = (__half*)p0;                     // P1 = X @ W1
    __half* bufP2 = (__half*)p0 + (size_t)NN * FH;   // P2 = dinv .* (H1 @ W2)
    __half* bufH  = (__half*)p1;                     // H1, then H2

    float* dinv_ptr;
    cudaGetSymbolAddress((void**)&dinv_ptr, g_dinv);

    cudaFuncSetAttribute(k_gemm_h,
                         cudaFuncAttributeMaxDynamicSharedMemorySize, SMEM_GEMM);

    int gblocks = (NN + 127) / 128;

    // fork: GEMM1 (P1 = X @ W1) at t=0, concurrent with the whole CSR build
    cudaEventRecord(hx.e0, 0);
    cudaStreamWaitEvent(hx.s2, hx.e0, 0);
    k_gemm_h<<<gblocks, 256, SMEM_GEMM, hx.s2>>>(x, 1, W1, bufP1, nullptr, NN);
    cudaEventRecord(hx.e1, hx.s2);

    // CSR build on the main (capturing) stream — memset + frozen 3-stage scan
    cudaMemsetAsync(pc, 0, NN * sizeof(int), 0);
    k_hist<<<(EE / 4 + 255) / 256, 256>>>(ei);
    k_block_reduce<<<NBLK, 256>>>();
    k_block_offsets<<<1, 256>>>();
    k_ptr_dinv<<<NBLK, 256>>>();
    k_scatter<<<(EE / 4 + 255) / 256, 256>>>(ei);

    // join GEMM1, then h1 = relu(agg(P1) + b1)  (dinv gathered per edge)
    cudaStreamWaitEvent(0, hx.e1, 0);
    k_agg_h<0><<<NN / 8, 256>>>(bufP1, bufH, b1);

    // layer 2: P2 = dinv .* (H1 @ W2); h2 = relu(di*(P2[i] + sum P2[s]) + b2)
    k_gemm_h<<<gblocks, 256, SMEM_GEMM>>>(bufH, 0, W2, bufP2, dinv_ptr, NN);
    k_agg_h<1><<<NN / 8, 256>>>(bufP2, bufH, b2);

    // mean pool + fc + log_softmax
    k_pool_fc<<<GG, 128>>>(bufH, batc, Wfc, bfc, out);
}

// round 15
// speedup vs baseline: 1.2300x; 1.0222x over previous
#include <cuda_runtime.h>
#include <cuda_fp16.h>
#include <cstdint>

#define NN   40000
#define EE   640000
#define FH   128
#define GG   256
#define NOUT 10
#define NBLK ((NN + 255) / 256)   // 157

// ---------------- scratch (static device globals; no allocs) ----------------
__device__ int   g_count[NN];
__device__ int   g_ptr[NN + 1];
__device__ int   g_cursor[NN];
__device__ float g_dinv[NN];
__device__ int   g_src[EE];
__device__ int   g_blocksum[NBLK];
__device__ float g_buf0[(size_t)NN * FH];  // halves: [P1 | P2]
__device__ float g_buf1[(size_t)NN * FH];  // halves: [H1, then H2]

__device__ __forceinline__ uint32_t h2u(__half2 h) { return *reinterpret_cast<uint32_t*>(&h); }
__device__ __forceinline__ __half2  u2h(uint32_t u) { return *reinterpret_cast<__half2*>(&u); }

// ---------------- CSR build ----------------
__global__ void k_zero_counts() {
    int i = blockIdx.x * blockDim.x + threadIdx.x;
    if (i < NN) g_count[i] = 0;
}

// 4 edges per thread via int4
__global__ void __launch_bounds__(256) k_hist(const int* __restrict__ ei) {
    int e4 = (blockIdx.x * blockDim.x + threadIdx.x) * 4;
    if (e4 < EE) {
        int4 c = *(const int4*)(ei + EE + e4);
        atomicAdd(&g_count[c.x], 1);
        atomicAdd(&g_count[c.y], 1);
        atomicAdd(&g_count[c.z], 1);
        atomicAdd(&g_count[c.w], 1);
    }
}

// stage 1: per-block sums of g_count
__global__ void __launch_bounds__(256) k_block_reduce() {
    __shared__ int ws[8];
    int i = blockIdx.x * 256 + threadIdx.x;
    int v = (i < NN) ? g_count[i] : 0;
#pragma unroll
    for (int o = 16; o > 0; o >>= 1) v += __shfl_down_sync(0xffffffffu, v, o);
    if ((threadIdx.x & 31) == 0) ws[threadIdx.x >> 5] = v;
    __syncthreads();
    if (threadIdx.x < 8) {
        int s = ws[threadIdx.x];
#pragma unroll
        for (int o = 4; o > 0; o >>= 1) s += __shfl_down_sync(0xffu, s, o);
        if (threadIdx.x == 0) g_blocksum[blockIdx.x] = s;
    }
}

// stage 2 (merged): each block derives its base by reducing the <=157 L2-hot
// block sums (one value per thread), then block-local scan -> ptr/cursor/dinv.
__global__ void __launch_bounds__(256) k_ptr_dinv() {
    __shared__ int ws[8];
    __shared__ int s_base;
    int b = blockIdx.x, t = threadIdx.x;
    int lane = t & 31, warp = t >> 5;

    // base = sum of blocksums[0..b-1]
    int v = (t < b && t < NBLK) ? g_blocksum[t] : 0;
#pragma unroll
    for (int o = 16; o > 0; o >>= 1) v += __shfl_down_sync(0xffffffffu, v, o);
    if (lane == 0) ws[warp] = v;
    __syncthreads();
    if (t == 0) {
        int s = 0;
#pragma unroll
        for (int k = 0; k < 8; k++) s += ws[k];
        s_base = s;
    }
    __syncthreads();
    int base = s_base;
    __syncthreads();  // ws reused below

    // block-local inclusive scan of counts
    int i = b * 256 + t;
    int c = (i < NN) ? g_count[i] : 0;
    int inc = c;
#pragma unroll
    for (int o = 1; o < 32; o <<= 1) {
        int u = __shfl_up_sync(0xffffffffu, inc, o);
        if (lane >= o) inc += u;
    }
    if (lane == 31) ws[warp] = inc;
    __syncthreads();
    if (t < 8) {
        int s = ws[t];
#pragma unroll
        for (int o = 1; o < 8; o <<= 1) {
            int u = __shfl_up_sync(0xffu, s, o);
            if (t >= o) s += u;
        }
        ws[t] = s;
    }
    __syncthreads();
    int ex = inc - c + (warp ? ws[warp - 1] : 0);

    if (i < NN) {
        int p = base + ex;
        g_ptr[i]    = p;
        g_cursor[i] = p;
        g_dinv[i]   = rsqrtf((float)(c + 1));
        if (i == NN - 1) g_ptr[NN] = p + c;
    }
}

// 4 edges per thread via int4 (int32 src — uint16 was a measured loser)
__global__ void __launch_bounds__(256) k_scatter(const int* __restrict__ ei) {
    int e4 = (blockIdx.x * blockDim.x + threadIdx.x) * 4;
    if (e4 < EE) {
        int4 r = *(const int4*)(ei + e4);
        int4 c = *(const int4*)(ei + EE + e4);
        int p0 = atomicAdd(&g_cursor[c.x], 1);
        int p1 = atomicAdd(&g_cursor[c.y], 1);
        int p2 = atomicAdd(&g_cursor[c.z], 1);
        int p3 = atomicAdd(&g_cursor[c.w], 1);
        g_src[p0] = r.x;
        g_src[p1] = r.y;
        g_src[p2] = r.z;
        g_src[p3] = r.w;
    }
}

// ---------------- fp16 mma GEMM: C[rows,128](fp16) = [row_scale .*] (A @ W) ----------------
#define AHS 136
#define BHS 136
#define SMEM_GEMM ((128 * AHS + 128 * BHS) * 2)

__device__ __forceinline__ void mma_f16(float* c, uint32_t a0, uint32_t a1, uint32_t a2,
                                        uint32_t a3, uint32_t b0, uint32_t b1) {
    asm volatile(
        "mma.sync.aligned.m16n8k16.row.col.f32.f16.f16.f32 "
        "{%0,%1,%2,%3}, {%4,%5,%6,%7}, {%8,%9}, {%0,%1,%2,%3};"
        : "+f"(c[0]), "+f"(c[1]), "+f"(c[2]), "+f"(c[3])
        : "r"(a0), "r"(a1), "r"(a2), "r"(a3), "r"(b0), "r"(b1));
}

__global__ void __launch_bounds__(256, 2) k_gemm_h(
    const void* __restrict__ Ain, int a_fp32,
    const float* __restrict__ W, __half* __restrict__ C,
    const float* __restrict__ row_scale, int M) {
    extern __shared__ __half sh[];
    __half* As = sh;
    __half* Bs = sh + 128 * AHS;
    int tid = threadIdx.x;
    int row0 = blockIdx.x * 128;

    if (a_fp32) {
        const float* A = (const float*)Ain;
        for (int i = tid; i < 4096; i += 256) {
            int r = i >> 5, c = (i & 31) << 2;
            int gr = row0 + r;
            float4 v = make_float4(0.f, 0.f, 0.f, 0.f);
            if (gr < M) v = *(const float4*)(A + (size_t)gr * 128 + c);
            uint2 u;
            u.x = h2u(__floats2half2_rn(v.x, v.y));
            u.y = h2u(__floats2half2_rn(v.z, v.w));
            *(uint2*)(As + r * AHS + c) = u;
        }
    } else {
        const __half* A = (const __half*)Ain;
        for (int i = tid; i < 4096; i += 256) {
            int r = i >> 5, c = (i & 31) << 2;
            int gr = row0 + r;
            uint2 u = make_uint2(0u, 0u);
            if (gr < M) u = *(const uint2*)(A + (size_t)gr * 128 + c);
            *(uint2*)(As + r * AHS + c) = u;
        }
    }

    for (int t = 0; t < 8; t++) {
        int idx = tid + t * 256;
        int k2 = (idx & 31) | (((idx >> 5) & 1) << 5);
        int n4 = (idx >> 6) << 2;
        int k = k2 * 2;
        const float* w0 = W + (size_t)k * 128 + n4;
        float4 r0 = *(const float4*)w0;
        float4 r1 = *(const float4*)(w0 + 128);
        *(uint32_t*)(Bs + (n4 + 0) * BHS + k) = h2u(__floats2half2_rn(r0.x, r1.x));
        *(uint32_t*)(Bs + (n4 + 1) * BHS + k) = h2u(__floats2half2_rn(r0.y, r1.y));
        *(uint32_t*)(Bs + (n4 + 2) * BHS + k) = h2u(__floats2half2_rn(r0.z, r1.z));
        *(uint32_t*)(Bs + (n4 + 3) * BHS + k) = h2u(__floats2half2_rn(r0.w, r1.w));
    }
    __syncthreads();

    int wid = tid >> 5, lane = tid & 31;
    int wm = (wid >> 2) * 64;
    int wn = (wid & 3) * 32;
    int g = lane >> 2, tg = lane & 3;

    float acc[4][4][4];
#pragma unroll
    for (int mt = 0; mt < 4; mt++)
#pragma unroll
        for (int nt = 0; nt < 4; nt++)
#pragma unroll
            for (int r = 0; r < 4; r++) acc[mt][nt][r] = 0.f;

#pragma unroll
    for (int k0 = 0; k0 < 128; k0 += 16) {
        uint32_t af[4][4];
#pragma unroll
        for (int mt = 0; mt < 4; mt++) {
            const __half* ap = As + (wm + mt * 16) * AHS + k0 + tg * 2;
            af[mt][0] = *(const uint32_t*)(ap + g * AHS);
            af[mt][1] = *(const uint32_t*)(ap + (g + 8) * AHS);
            af[mt][2] = *(const uint32_t*)(ap + g * AHS + 8);
            af[mt][3] = *(const uint32_t*)(ap + (g + 8) * AHS + 8);
        }
        uint32_t bf[4][2];
#pragma unroll
        for (int nt = 0; nt < 4; nt++) {
            const __half* bp = Bs + (wn + nt * 8 + g) * BHS + k0 + tg * 2;
            bf[nt][0] = *(const uint32_t*)(bp);
            bf[nt][1] = *(const uint32_t*)(bp + 8);
        }
#pragma unroll
        for (int mt = 0; mt < 4; mt++)
#pragma unroll
            for (int nt = 0; nt < 4; nt++)
                mma_f16(acc[mt][nt], af[mt][0], af[mt][1], af[mt][2], af[mt][3],
                        bf[nt][0], bf[nt][1]);
    }

#pragma unroll
    for (int nt = 0; nt < 4; nt++) {
        int col = wn + nt * 8 + tg * 2;
#pragma unroll
        for (int mt = 0; mt < 4; mt++) {
            int r0 = row0 + wm + mt * 16 + g;
            if (r0 < M) {
                float s0 = row_scale ? row_scale[r0] : 1.0f;
                *(uint32_t*)(C + (size_t)r0 * 128 + col) =
                    h2u(__floats2half2_rn(acc[mt][nt][0] * s0, acc[mt][nt][1] * s0));
            }
            int r1 = r0 + 8;
            if (r1 < M) {
                float s1 = row_scale ? row_scale[r1] : 1.0f;
                *(uint32_t*)(C + (size_t)r1 * 128 + col) =
                    h2u(__floats2half2_rn(acc[mt][nt][2] * s1, acc[mt][nt][3] * s1));
            }
        }
    }
}

// ---------------- fp16 aggregation + bias + relu (8-wide MLP inner loop) ----------------
// PRESCALED=0: Hout[i] = relu(di*(di*P[i] + sum_s dinv[s]*P[s]) + b)
// PRESCALED=1: rows of P prescaled by dinv -> Hout[i] = relu(di*(P[i] + sum_s P[s]) + b)
template <int PRESCALED>
__global__ void __launch_bounds__(256) k_agg_h(
    const __half* __restrict__ P, __half* __restrict__ Hout,
    const float* __restrict__ bias) {
    int node = (blockIdx.x * blockDim.x + threadIdx.x) >> 5;
    int lane = threadIdx.x & 31;
    if (node >= NN) return;
    int c4 = lane * 4;
    float di = g_dinv[node];

    uint2 sv = *(const uint2*)(P + (size_t)node * FH + c4);
    float2 f0 = __half22float2(u2h(sv.x));
    float2 f1 = __half22float2(u2h(sv.y));
    float selfs = PRESCALED ? 1.0f : di;
    float ax = selfs * f0.x, ay = selfs * f0.y, az = selfs * f1.x, aw = selfs * f1.y;

    int beg = g_ptr[node], end = g_ptr[node + 1];
    int j = beg;

    for (; j + 8 <= end; j += 8) {
        int s[8];
#pragma unroll
        for (int q = 0; q < 8; q++) s[q] = g_src[j + q];
        float d[8];
#pragma unroll
        for (int q = 0; q < 8; q++) d[q] = PRESCALED ? 1.0f : g_dinv[s[q]];
        uint2 v[8];
#pragma unroll
        for (int q = 0; q < 8; q++) v[q] = *(const uint2*)(P + (size_t)s[q] * FH + c4);
#pragma unroll
        for (int q = 0; q < 8; q++) {
            float2 a = __half22float2(u2h(v[q].x));
            float2 b = __half22float2(u2h(v[q].y));
            if (PRESCALED) {
                ax += a.x; ay += a.y; az += b.x; aw += b.y;
            } else {
                ax = fmaf(d[q], a.x, ax); ay = fmaf(d[q], a.y, ay);
                az = fmaf(d[q], b.x, az); aw = fmaf(d[q], b.y, aw);
            }
        }
    }
    for (; j + 4 <= end; j += 4) {
        int s[4];
#pragma unroll
        for (int q = 0; q < 4; q++) s[q] = g_src[j + q];
        float d[4];
#pragma unroll
        for (int q = 0; q < 4; q++) d[q] = PRESCALED ? 1.0f : g_dinv[s[q]];
        uint2 v[4];
#pragma unroll
        for (int q = 0; q < 4; q++) v[q] = *(const uint2*)(P + (size_t)s[q] * FH + c4);
#pragma unroll
        for (int q = 0; q < 4; q++) {
            float2 a = __half22float2(u2h(v[q].x));
            float2 b = __half22float2(u2h(v[q].y));
            if (PRESCALED) {
                ax += a.x; ay += a.y; az += b.x; aw += b.y;
            } else {
                ax = fmaf(d[q], a.x, ax); ay = fmaf(d[q], a.y, ay);
                az = fmaf(d[q], b.x, az); aw = fmaf(d[q], b.y, aw);
            }
        }
    }
    for (; j < end; j++) {
        int s0 = g_src[j];
        float d0 = PRESCALED ? 1.0f : g_dinv[s0];
        uint2 v0 = *(const uint2*)(P + (size_t)s0 * FH + c4);
        float2 a0 = __half22float2(u2h(v0.x)), b0 = __half22float2(u2h(v0.y));
        ax = fmaf(d0, a0.x, ax); ay = fmaf(d0, a0.y, ay);
        az = fmaf(d0, b0.x, az); aw = fmaf(d0, b0.y, aw);
    }

    float4 bb = *(const float4*)(bias + c4);
    float ox = fmaxf(fmaf(ax, di, bb.x), 0.f);
    float oy = fmaxf(fmaf(ay, di, bb.y), 0.f);
    float oz = fmaxf(fmaf(az, di, bb.z), 0.f);
    float ow = fmaxf(fmaf(aw, di, bb.w), 0.f);
    uint2 o;
    o.x = h2u(__floats2half2_rn(ox, oy));
    o.y = h2u(__floats2half2_rn(oz, ow));
    *(uint2*)(Hout + (size_t)node * FH + c4) = o;
}

// ---------------- mean pool (batch sorted) + FC + log_softmax ----------------
__device__ __forceinline__ int lower_bound_i(const int* __restrict__ b, int n, int key) {
    int lo = 0, hi = n;
    while (lo < hi) {
        int mid = (lo + hi) >> 1;
        if (b[mid] < key) lo = mid + 1; else hi = mid;
    }
    return lo;
}

__global__ void __launch_bounds__(128) k_pool_fc(
    const __half* __restrict__ H2, const int* __restrict__ batch,
    const float* __restrict__ Wfc, const float* __restrict__ bfc,
    float* __restrict__ out) {
    int g = blockIdx.x;
    int tid = threadIdx.x;
    __shared__ float pooled[FH];
    __shared__ float logit[NOUT];
    __shared__ int range[2];

    if (tid == 0) {
        range[0] = lower_bound_i(batch, NN, g);
        range[1] = lower_bound_i(batch, NN, g + 1);
    }
    __syncthreads();
    int lo = range[0], hi = range[1];

    float s = 0.f;
    for (int n = lo; n < hi; n++) s += __half2float(H2[(size_t)n * FH + tid]);
    pooled[tid] = s / fmaxf((float)(hi - lo), 1.0f);
    __syncthreads();

    if (tid < NOUT) {
        float acc = bfc[tid];
        for (int k = 0; k < FH; k++) acc = fmaf(pooled[k], Wfc[k * NOUT + tid], acc);
        logit[tid] = acc;
    }
    __syncthreads();

    if (tid == 0) {
        float m = -1e30f;
        for (int o = 0; o < NOUT; o++) m = fmaxf(m, logit[o]);
        float se = 0.f;
        for (int o = 0; o < NOUT; o++) se += expf(logit[o] - m);
        float lse = m + logf(se);
        for (int o = 0; o < NOUT; o++) out[g * NOUT + o] = logit[o] - lse;
    }
}

// ---------------- launch (R8/R11 schedule, verified optimum) ----------------
struct HxRes {
    cudaStream_t s2;
    cudaEvent_t e0, e1;
    HxRes() {
        cudaStreamCreateWithFlags(&s2, cudaStreamNonBlocking);
        cudaEventCreateWithFlags(&e0, cudaEventDisableTiming);
        cudaEventCreateWithFlags(&e1, cudaEventDisableTiming);
    }
};

extern "C" void kernel_launch(void* const* d_in, const int* in_sizes, int n_in,
                              void* d_out, int out_size) {
    static HxRes hx;

    const float* x    = (const float*)d_in[0];
    const int*   ei   = (const int*)d_in[1];
    const int*   batc = (const int*)d_in[2];
    const float* W1   = (const float*)d_in[3];
    const float* b1   = (const float*)d_in[4];
    const float* W2   = (const float*)d_in[5];
    const float* b2   = (const float*)d_in[6];
    const float* Wfc  = (const float*)d_in[7];
    const float* bfc  = (const float*)d_in[8];
    float* out = (float*)d_out;

    void *p0, *p1;
    cudaGetSymbolAddress(&p0, g_buf0);
    cudaGetSymbolAddress(&p1, g_buf1);
    __half* bufP1 = (__half*)p0;                     // P1 = X @ W1
    __half* bufP2 = (__half*)p0 + (size_t)NN * FH;   // P2 = dinv .* (H1 @ W2)
    __half* bufH  = (__half*)p1;                     // H1, then H2

    float* dinv_ptr;
    cudaGetSymbolAddress((void**)&dinv_ptr, g_dinv);

    cudaFuncSetAttribute(k_gemm_h,
                         cudaFuncAttributeMaxDynamicSharedMemorySize, SMEM_GEMM);

    int gblocks = (NN + 127) / 128;

    // fork: GEMM1 (P1 = X @ W1) at t=0, concurrent with the whole CSR build
    cudaEventRecord(hx.e0, 0);
    cudaStreamWaitEvent(hx.s2, hx.e0, 0);
    k_gemm_h<<<gblocks, 256, SMEM_GEMM, hx.s2>>>(x, 1, W1, bufP1, nullptr, NN);
    cudaEventRecord(hx.e1, hx.s2);

    // CSR build on the main (capturing) stream — 2-stage scan (merged offsets)
    k_zero_counts<<<NBLK, 256>>>();
    k_hist<<<(EE / 4 + 255) / 256, 256>>>(ei);
    k_block_reduce<<<NBLK, 256>>>();
    k_ptr_dinv<<<NBLK, 256>>>();
    k_scatter<<<(EE / 4 + 255) / 256, 256>>>(ei);

    // join GEMM1, then h1 = relu(agg(P1) + b1)  (dinv gathered per edge)
    cudaStreamWaitEvent(0, hx.e1, 0);
    k_agg_h<0><<<NN / 8, 256>>>(bufP1, bufH, b1);

    // layer 2: P2 = dinv .* (H1 @ W2); h2 = relu(di*(P2[i] + sum P2[s]) + b2)
    k_gemm_h<<<gblocks, 256, SMEM_GEMM>>>(bufH, 0, W2, bufP2, dinv_ptr, NN);
    k_agg_h<1><<<NN / 8, 256>>>(bufP2, bufH, b2);

    // mean pool + fc + log_softmax
    k_pool_fc<<<GG, 128>>>(bufH, batc, Wfc, bfc, out);
}

// round 16
// speedup vs baseline: 1.2339x; 1.0031x over previous
#include <cuda_runtime.h>
#include <cuda_fp16.h>
#include <cstdint>

#define NN   40000
#define EE   640000
#define FH   128
#define GG   256
#define NOUT 10
#define NBLK ((NN + 255) / 256)   // 157

// ---------------- scratch (static device globals; no allocs) ----------------
// g_count is zero at module load and re-zeroed by k_ptr_dinv after each use,
// so no explicit zeroing kernel is needed (deterministic across replays).
__device__ int   g_count[NN];
__device__ int   g_ptr[NN + 1];
__device__ int   g_cursor[NN];
__device__ float g_dinv[NN];
__device__ int   g_src[EE];
__device__ int   g_blocksum[NBLK];
__device__ float g_buf0[(size_t)NN * FH];  // halves: [P1 | P2]
__device__ float g_buf1[(size_t)NN * FH];  // halves: [H1, then H2]

__device__ __forceinline__ uint32_t h2u(__half2 h) { return *reinterpret_cast<uint32_t*>(&h); }
__device__ __forceinline__ __half2  u2h(uint32_t u) { return *reinterpret_cast<__half2*>(&u); }

// ---------------- CSR build ----------------
// 4 edges per thread via int4
__global__ void __launch_bounds__(256) k_hist(const int* __restrict__ ei) {
    int e4 = (blockIdx.x * blockDim.x + threadIdx.x) * 4;
    if (e4 < EE) {
        int4 c = *(const int4*)(ei + EE + e4);
        atomicAdd(&g_count[c.x], 1);
        atomicAdd(&g_count[c.y], 1);
        atomicAdd(&g_count[c.z], 1);
        atomicAdd(&g_count[c.w], 1);
    }
}

// stage 1: per-block sums of g_count
__global__ void __launch_bounds__(256) k_block_reduce() {
    __shared__ int ws[8];
    int i = blockIdx.x * 256 + threadIdx.x;
    int v = (i < NN) ? g_count[i] : 0;
#pragma unroll
    for (int o = 16; o > 0; o >>= 1) v += __shfl_down_sync(0xffffffffu, v, o);
    if ((threadIdx.x & 31) == 0) ws[threadIdx.x >> 5] = v;
    __syncthreads();
    if (threadIdx.x < 8) {
        int s = ws[threadIdx.x];
#pragma unroll
        for (int o = 4; o > 0; o >>= 1) s += __shfl_down_sync(0xffu, s, o);
        if (threadIdx.x == 0) g_blocksum[blockIdx.x] = s;
    }
}

// stage 2 (merged): each block derives its base by reducing the <=157 L2-hot
// block sums, then block-local scan -> ptr/cursor/dinv. Zeroes g_count after
// the last read so the next invocation starts clean (no zeroing kernel).
__global__ void __launch_bounds__(256) k_ptr_dinv() {
    __shared__ int ws[8];
    __shared__ int s_base;
    int b = blockIdx.x, t = threadIdx.x;
    int lane = t & 31, warp = t >> 5;

    // base = sum of blocksums[0..b-1]
    int v = (t < b && t < NBLK) ? g_blocksum[t] : 0;
#pragma unroll
    for (int o = 16; o > 0; o >>= 1) v += __shfl_down_sync(0xffffffffu, v, o);
    if (lane == 0) ws[warp] = v;
    __syncthreads();
    if (t == 0) {
        int s = 0;
#pragma unroll
        for (int k = 0; k < 8; k++) s += ws[k];
        s_base = s;
    }
    __syncthreads();
    int base = s_base;
    __syncthreads();  // ws reused below

    // block-local inclusive scan of counts
    int i = b * 256 + t;
    int c = (i < NN) ? g_count[i] : 0;
    if (i < NN) g_count[i] = 0;   // self-zero for the next call
    int inc = c;
#pragma unroll
    for (int o = 1; o < 32; o <<= 1) {
        int u = __shfl_up_sync(0xffffffffu, inc, o);
        if (lane >= o) inc += u;
    }
    if (lane == 31) ws[warp] = inc;
    __syncthreads();
    if (t < 8) {
        int s = ws[t];
#pragma unroll
        for (int o = 1; o < 8; o <<= 1) {
            int u = __shfl_up_sync(0xffu, s, o);
            if (t >= o) s += u;
        }
        ws[t] = s;
    }
    __syncthreads();
    int ex = inc - c + (warp ? ws[warp - 1] : 0);

    if (i < NN) {
        int p = base + ex;
        g_ptr[i]    = p;
        g_cursor[i] = p;
        g_dinv[i]   = rsqrtf((float)(c + 1));
        if (i == NN - 1) g_ptr[NN] = p + c;
    }
}

// 4 edges per thread via int4 (int32 src — uint16 was a measured loser)
__global__ void __launch_bounds__(256) k_scatter(const int* __restrict__ ei) {
    int e4 = (blockIdx.x * blockDim.x + threadIdx.x) * 4;
    if (e4 < EE) {
        int4 r = *(const int4*)(ei + e4);
        int4 c = *(const int4*)(ei + EE + e4);
        int p0 = atomicAdd(&g_cursor[c.x], 1);
        int p1 = atomicAdd(&g_cursor[c.y], 1);
        int p2 = atomicAdd(&g_cursor[c.z], 1);
        int p3 = atomicAdd(&g_cursor[c.w], 1);
        g_src[p0] = r.x;
        g_src[p1] = r.y;
        g_src[p2] = r.z;
        g_src[p3] = r.w;
    }
}

// ---------------- fp16 mma GEMM: C[rows,128](fp16) = [row_scale .*] (A @ W) ----------------
#define AHS 136
#define BHS 136
#define SMEM_GEMM ((128 * AHS + 128 * BHS) * 2)

__device__ __forceinline__ void mma_f16(float* c, uint32_t a0, uint32_t a1, uint32_t a2,
                                        uint32_t a3, uint32_t b0, uint32_t b1) {
    asm volatile(
        "mma.sync.aligned.m16n8k16.row.col.f32.f16.f16.f32 "
        "{%0,%1,%2,%3}, {%4,%5,%6,%7}, {%8,%9}, {%0,%1,%2,%3};"
        : "+f"(c[0]), "+f"(c[1]), "+f"(c[2]), "+f"(c[3])
        : "r"(a0), "r"(a1), "r"(a2), "r"(a3), "r"(b0), "r"(b1));
}

__global__ void __launch_bounds__(256, 2) k_gemm_h(
    const void* __restrict__ Ain, int a_fp32,
    const float* __restrict__ W, __half* __restrict__ C,
    const float* __restrict__ row_scale, int M) {
    extern __shared__ __half sh[];
    __half* As = sh;
    __half* Bs = sh + 128 * AHS;
    int tid = threadIdx.x;
    int row0 = blockIdx.x * 128;

    if (a_fp32) {
        const float* A = (const float*)Ain;
        for (int i = tid; i < 4096; i += 256) {
            int r = i >> 5, c = (i & 31) << 2;
            int gr = row0 + r;
            float4 v = make_float4(0.f, 0.f, 0.f, 0.f);
            if (gr < M) v = *(const float4*)(A + (size_t)gr * 128 + c);
            uint2 u;
            u.x = h2u(__floats2half2_rn(v.x, v.y));
            u.y = h2u(__floats2half2_rn(v.z, v.w));
            *(uint2*)(As + r * AHS + c) = u;
        }
    } else {
        const __half* A = (const __half*)Ain;
        for (int i = tid; i < 4096; i += 256) {
            int r = i >> 5, c = (i & 31) << 2;
            int gr = row0 + r;
            uint2 u = make_uint2(0u, 0u);
            if (gr < M) u = *(const uint2*)(A + (size_t)gr * 128 + c);
            *(uint2*)(As + r * AHS + c) = u;
        }
    }

    for (int t = 0; t < 8; t++) {
        int idx = tid + t * 256;
        int k2 = (idx & 31) | (((idx >> 5) & 1) << 5);
        int n4 = (idx >> 6) << 2;
        int k = k2 * 2;
        const float* w0 = W + (size_t)k * 128 + n4;
        float4 r0 = *(const float4*)w0;
        float4 r1 = *(const float4*)(w0 + 128);
        *(uint32_t*)(Bs + (n4 + 0) * BHS + k) = h2u(__floats2half2_rn(r0.x, r1.x));
        *(uint32_t*)(Bs + (n4 + 1) * BHS + k) = h2u(__floats2half2_rn(r0.y, r1.y));
        *(uint32_t*)(Bs + (n4 + 2) * BHS + k) = h2u(__floats2half2_rn(r0.z, r1.z));
        *(uint32_t*)(Bs + (n4 + 3) * BHS + k) = h2u(__floats2half2_rn(r0.w, r1.w));
    }
    __syncthreads();

    int wid = tid >> 5, lane = tid & 31;
    int wm = (wid >> 2) * 64;
    int wn = (wid & 3) * 32;
    int g = lane >> 2, tg = lane & 3;

    float acc[4][4][4];
#pragma unroll
    for (int mt = 0; mt < 4; mt++)
#pragma unroll
        for (int nt = 0; nt < 4; nt++)
#pragma unroll
            for (int r = 0; r < 4; r++) acc[mt][nt][r] = 0.f;

#pragma unroll
    for (int k0 = 0; k0 < 128; k0 += 16) {
        uint32_t af[4][4];
#pragma unroll
        for (int mt = 0; mt < 4; mt++) {
            const __half* ap = As + (wm + mt * 16) * AHS + k0 + tg * 2;
            af[mt][0] = *(const uint32_t*)(ap + g * AHS);
            af[mt][1] = *(const uint32_t*)(ap + (g + 8) * AHS);
            af[mt][2] = *(const uint32_t*)(ap + g * AHS + 8);
            af[mt][3] = *(const uint32_t*)(ap + (g + 8) * AHS + 8);
        }
        uint32_t bf[4][2];
#pragma unroll
        for (int nt = 0; nt < 4; nt++) {
            const __half* bp = Bs + (wn + nt * 8 + g) * BHS + k0 + tg * 2;
            bf[nt][0] = *(const uint32_t*)(bp);
            bf[nt][1] = *(const uint32_t*)(bp + 8);
        }
#pragma unroll
        for (int mt = 0; mt < 4; mt++)
#pragma unroll
            for (int nt = 0; nt < 4; nt++)
                mma_f16(acc[mt][nt], af[mt][0], af[mt][1], af[mt][2], af[mt][3],
                        bf[nt][0], bf[nt][1]);
    }

#pragma unroll
    for (int nt = 0; nt < 4; nt++) {
        int col = wn + nt * 8 + tg * 2;
#pragma unroll
        for (int mt = 0; mt < 4; mt++) {
            int r0 = row0 + wm + mt * 16 + g;
            if (r0 < M) {
                float s0 = row_scale ? row_scale[r0] : 1.0f;
                *(uint32_t*)(C + (size_t)r0 * 128 + col) =
                    h2u(__floats2half2_rn(acc[mt][nt][0] * s0, acc[mt][nt][1] * s0));
            }
            int r1 = r0 + 8;
            if (r1 < M) {
                float s1 = row_scale ? row_scale[r1] : 1.0f;
                *(uint32_t*)(C + (size_t)r1 * 128 + col) =
                    h2u(__floats2half2_rn(acc[mt][nt][2] * s1, acc[mt][nt][3] * s1));
            }
        }
    }
}

// ---------------- fp16 aggregation + bias + relu (8-wide MLP inner loop) ----------------
// PRESCALED=0: Hout[i] = relu(di*(di*P[i] + sum_s dinv[s]*P[s]) + b)
// PRESCALED=1: rows of P prescaled by dinv -> Hout[i] = relu(di*(P[i] + sum_s P[s]) + b)
template <int PRESCALED>
__global__ void __launch_bounds__(256) k_agg_h(
    const __half* __restrict__ P, __half* __restrict__ Hout,
    const float* __restrict__ bias) {
    int node = (blockIdx.x * blockDim.x + threadIdx.x) >> 5;
    int lane = threadIdx.x & 31;
    if (node >= NN) return;
    int c4 = lane * 4;
    float di = g_dinv[node];

    uint2 sv = *(const uint2*)(P + (size_t)node * FH + c4);
    float2 f0 = __half22float2(u2h(sv.x));
    float2 f1 = __half22float2(u2h(sv.y));
    float selfs = PRESCALED ? 1.0f : di;
    float ax = selfs * f0.x, ay = selfs * f0.y, az = selfs * f1.x, aw = selfs * f1.y;

    int beg = g_ptr[node], end = g_ptr[node + 1];
    int j = beg;

    for (; j + 8 <= end; j += 8) {
        int s[8];
#pragma unroll
        for (int q = 0; q < 8; q++) s[q] = g_src[j + q];
        float d[8];
#pragma unroll
        for (int q = 0; q < 8; q++) d[q] = PRESCALED ? 1.0f : g_dinv[s[q]];
        uint2 v[8];
#pragma unroll
        for (int q = 0; q < 8; q++) v[q] = *(const uint2*)(P + (size_t)s[q] * FH + c4);
#pragma unroll
        for (int q = 0; q < 8; q++) {
            float2 a = __half22float2(u2h(v[q].x));
            float2 b = __half22float2(u2h(v[q].y));
            if (PRESCALED) {
                ax += a.x; ay += a.y; az += b.x; aw += b.y;
            } else {
                ax = fmaf(d[q], a.x, ax); ay = fmaf(d[q], a.y, ay);
                az = fmaf(d[q], b.x, az); aw = fmaf(d[q], b.y, aw);
            }
        }
    }
    for (; j + 4 <= end; j += 4) {
        int s[4];
#pragma unroll
        for (int q = 0; q < 4; q++) s[q] = g_src[j + q];
        float d[4];
#pragma unroll
        for (int q = 0; q < 4; q++) d[q] = PRESCALED ? 1.0f : g_dinv[s[q]];
        uint2 v[4];
#pragma unroll
        for (int q = 0; q < 4; q++) v[q] = *(const uint2*)(P + (size_t)s[q] * FH + c4);
#pragma unroll
        for (int q = 0; q < 4; q++) {
            float2 a = __half22float2(u2h(v[q].x));
            float2 b = __half22float2(u2h(v[q].y));
            if (PRESCALED) {
                ax += a.x; ay += a.y; az += b.x; aw += b.y;
            } else {
                ax = fmaf(d[q], a.x, ax); ay = fmaf(d[q], a.y, ay);
                az = fmaf(d[q], b.x, az); aw = fmaf(d[q], b.y, aw);
            }
        }
    }
    for (; j < end; j++) {
        int s0 = g_src[j];
        float d0 = PRESCALED ? 1.0f : g_dinv[s0];
        uint2 v0 = *(const uint2*)(P + (size_t)s0 * FH + c4);
        float2 a0 = __half22float2(u2h(v0.x)), b0 = __half22float2(u2h(v0.y));
        ax = fmaf(d0, a0.x, ax); ay = fmaf(d0, a0.y, ay);
        az = fmaf(d0, b0.x, az); aw = fmaf(d0, b0.y, aw);
    }

    float4 bb = *(const float4*)(bias + c4);
    float ox = fmaxf(fmaf(ax, di, bb.x), 0.f);
    float oy = fmaxf(fmaf(ay, di, bb.y), 0.f);
    float oz = fmaxf(fmaf(az, di, bb.z), 0.f);
    float ow = fmaxf(fmaf(aw, di, bb.w), 0.f);
    uint2 o;
    o.x = h2u(__floats2half2_rn(ox, oy));
    o.y = h2u(__floats2half2_rn(oz, ow));
    *(uint2*)(Hout + (size_t)node * FH + c4) = o;
}

// ---------------- mean pool (batch sorted) + FC + log_softmax ----------------
__device__ __forceinline__ int lower_bound_i(const int* __restrict__ b, int n, int key) {
    int lo = 0, hi = n;
    while (lo < hi) {
        int mid = (lo + hi) >> 1;
        if (b[mid] < key) lo = mid + 1; else hi = mid;
    }
    return lo;
}

__global__ void __launch_bounds__(128) k_pool_fc(
    const __half* __restrict__ H2, const int* __restrict__ batch,
    const float* __restrict__ Wfc, const float* __restrict__ bfc,
    float* __restrict__ out) {
    int g = blockIdx.x;
    int tid = threadIdx.x;
    __shared__ float pooled[FH];
    __shared__ float logit[NOUT];
    __shared__ int range[2];

    if (tid == 0) {
        range[0] = lower_bound_i(batch, NN, g);
        range[1] = lower_bound_i(batch, NN, g + 1);
    }
    __syncthreads();
    int lo = range[0], hi = range[1];

    float s = 0.f;
    for (int n = lo; n < hi; n++) s += __half2float(H2[(size_t)n * FH + tid]);
    pooled[tid] = s / fmaxf((float)(hi - lo), 1.0f);
    __syncthreads();

    if (tid < NOUT) {
        float acc = bfc[tid];
        for (int k = 0; k < FH; k++) acc = fmaf(pooled[k], Wfc[k * NOUT + tid], acc);
        logit[tid] = acc;
    }
    __syncthreads();

    if (tid == 0) {
        float m = -1e30f;
        for (int o = 0; o < NOUT; o++) m = fmaxf(m, logit[o]);
        float se = 0.f;
        for (int o = 0; o < NOUT; o++) se += expf(logit[o] - m);
        float lse = m + logf(se);
        for (int o = 0; o < NOUT; o++) out[g * NOUT + o] = logit[o] - lse;
    }
}

// ---------------- launch (R15 schedule minus the zeroing kernel) ----------------
struct HxRes {
    cudaStream_t s2;
    cudaEvent_t e0, e1;
    HxRes() {
        cudaStreamCreateWithFlags(&s2, cudaStreamNonBlocking);
        cudaEventCreateWithFlags(&e0, cudaEventDisableTiming);
        cudaEventCreateWithFlags(&e1, cudaEventDisableTiming);
    }
};

extern "C" void kernel_launch(void* const* d_in, const int* in_sizes, int n_in,
                              void* d_out, int out_size) {
    static HxRes hx;

    const float* x    = (const float*)d_in[0];
    const int*   ei   = (const int*)d_in[1];
    const int*   batc = (const int*)d_in[2];
    const float* W1   = (const float*)d_in[3];
    const float* b1   = (const float*)d_in[4];
    const float* W2   = (const float*)d_in[5];
    const float* b2   = (const float*)d_in[6];
    const float* Wfc  = (const float*)d_in[7];
    const float* bfc  = (const float*)d_in[8];
    float* out = (float*)d_out;

    void *p0, *p1;
    cudaGetSymbolAddress(&p0, g_buf0);
    cudaGetSymbolAddress(&p1, g_buf1);
    __half* bufP1 = (__half*)p0;                     // P1 = X @ W1
    __half* bufP2 = (__half*)p0 + (size_t)NN * FH;   // P2 = dinv .* (H1 @ W2)
    __half* bufH  = (__half*)p1;                     // H1, then H2

    float* dinv_ptr;
    cudaGetSymbolAddress((void**)&dinv_ptr, g_dinv);

    cudaFuncSetAttribute(k_gemm_h,
                         cudaFuncAttributeMaxDynamicSharedMemorySize, SMEM_GEMM);

    int gblocks = (NN + 127) / 128;

    // fork: GEMM1 (P1 = X @ W1) at t=0, concurrent with the whole CSR build
    cudaEventRecord(hx.e0, 0);
    cudaStreamWaitEvent(hx.s2, hx.e0, 0);
    k_gemm_h<<<gblocks, 256, SMEM_GEMM, hx.s2>>>(x, 1, W1, bufP1, nullptr, NN);
    cudaEventRecord(hx.e1, hx.s2);

    // CSR build on the main (capturing) stream — counts are pre-zeroed
    // (module init on first call, self-zeroed by k_ptr_dinv afterwards)
    k_hist<<<(EE / 4 + 255) / 256, 256>>>(ei);
    k_block_reduce<<<NBLK, 256>>>();
    k_ptr_dinv<<<NBLK, 256>>>();
    k_scatter<<<(EE / 4 + 255) / 256, 256>>>(ei);

    // join GEMM1, then h1 = relu(agg(P1) + b1)  (dinv gathered per edge)
    cudaStreamWaitEvent(0, hx.e1, 0);
    k_agg_h<0><<<NN / 8, 256>>>(bufP1, bufH, b1);

    // layer 2: P2 = dinv .* (H1 @ W2); h2 = relu(di*(P2[i] + sum P2[s]) + b2)
    k_gemm_h<<<gblocks, 256, SMEM_GEMM>>>(bufH, 0, W2, bufP2, dinv_ptr, NN);
    k_agg_h<1><<<NN / 8, 256>>>(bufP2, bufH, b2);

    // mean pool + fc + log_softmax
    k_pool_fc<<<GG, 128>>>(bufH, batc, Wfc, bfc, out);
}

// round 17
// speedup vs baseline: 1.2714x; 1.0303x over previous
#include <cuda_runtime.h>
#include <cuda_fp16.h>
#include <cstdint>

#define NN   40000
#define EE   640000
#define FH   128
#define GG   256
#define NOUT 10
#define NBLK ((NN + 255) / 256)   // 157

// ---------------- scratch (static device globals; no allocs) ----------------
// g_count / g_pool are zero at module load and re-zeroed by their last readers
// each call, so no explicit zeroing kernels are needed (deterministic replay).
__device__ int   g_count[NN];
__device__ int   g_ptr[NN + 1];
__device__ int   g_cursor[NN];
__device__ float g_dinv[NN];
__device__ int   g_src[EE];
__device__ int   g_blocksum[NBLK];
__device__ float g_pool[GG * FH];
__device__ float g_buf0[(size_t)NN * FH];  // halves: [P1 | P2]
__device__ float g_buf1[(size_t)NN * FH];  // halves: [H1]

__device__ __forceinline__ uint32_t h2u(__half2 h) { return *reinterpret_cast<uint32_t*>(&h); }
__device__ __forceinline__ __half2  u2h(uint32_t u) { return *reinterpret_cast<__half2*>(&u); }

// ---------------- CSR build (R15/R16-frozen) ----------------
// 4 edges per thread via int4
__global__ void __launch_bounds__(256) k_hist(const int* __restrict__ ei) {
    int e4 = (blockIdx.x * blockDim.x + threadIdx.x) * 4;
    if (e4 < EE) {
        int4 c = *(const int4*)(ei + EE + e4);
        atomicAdd(&g_count[c.x], 1);
        atomicAdd(&g_count[c.y], 1);
        atomicAdd(&g_count[c.z], 1);
        atomicAdd(&g_count[c.w], 1);
    }
}

__global__ void __launch_bounds__(256) k_block_reduce() {
    __shared__ int ws[8];
    int i = blockIdx.x * 256 + threadIdx.x;
    int v = (i < NN) ? g_count[i] : 0;
#pragma unroll
    for (int o = 16; o > 0; o >>= 1) v += __shfl_down_sync(0xffffffffu, v, o);
    if ((threadIdx.x & 31) == 0) ws[threadIdx.x >> 5] = v;
    __syncthreads();
    if (threadIdx.x < 8) {
        int s = ws[threadIdx.x];
#pragma unroll
        for (int o = 4; o > 0; o >>= 1) s += __shfl_down_sync(0xffu, s, o);
        if (threadIdx.x == 0) g_blocksum[blockIdx.x] = s;
    }
}

// merged: base from <=157 L2-hot block sums, then block-local scan; self-zeros counts.
__global__ void __launch_bounds__(256) k_ptr_dinv() {
    __shared__ int ws[8];
    __shared__ int s_base;
    int b = blockIdx.x, t = threadIdx.x;
    int lane = t & 31, warp = t >> 5;

    int v = (t < b && t < NBLK) ? g_blocksum[t] : 0;
#pragma unroll
    for (int o = 16; o > 0; o >>= 1) v += __shfl_down_sync(0xffffffffu, v, o);
    if (lane == 0) ws[warp] = v;
    __syncthreads();
    if (t == 0) {
        int s = 0;
#pragma unroll
        for (int k = 0; k < 8; k++) s += ws[k];
        s_base = s;
    }
    __syncthreads();
    int base = s_base;
    __syncthreads();  // ws reused below

    int i = b * 256 + t;
    int c = (i < NN) ? g_count[i] : 0;
    if (i < NN) g_count[i] = 0;   // self-zero for the next call
    int inc = c;
#pragma unroll
    for (int o = 1; o < 32; o <<= 1) {
        int u = __shfl_up_sync(0xffffffffu, inc, o);
        if (lane >= o) inc += u;
    }
    if (lane == 31) ws[warp] = inc;
    __syncthreads();
    if (t < 8) {
        int s = ws[t];
#pragma unroll
        for (int o = 1; o < 8; o <<= 1) {
            int u = __shfl_up_sync(0xffu, s, o);
            if (t >= o) s += u;
        }
        ws[t] = s;
    }
    __syncthreads();
    int ex = inc - c + (warp ? ws[warp - 1] : 0);

    if (i < NN) {
        int p = base + ex;
        g_ptr[i]    = p;
        g_cursor[i] = p;
        g_dinv[i]   = rsqrtf((float)(c + 1));
        if (i == NN - 1) g_ptr[NN] = p + c;
    }
}

// 4 edges per thread via int4
__global__ void __launch_bounds__(256) k_scatter(const int* __restrict__ ei) {
    int e4 = (blockIdx.x * blockDim.x + threadIdx.x) * 4;
    if (e4 < EE) {
        int4 r = *(const int4*)(ei + e4);
        int4 c = *(const int4*)(ei + EE + e4);
        int p0 = atomicAdd(&g_cursor[c.x], 1);
        int p1 = atomicAdd(&g_cursor[c.y], 1);
        int p2 = atomicAdd(&g_cursor[c.z], 1);
        int p3 = atomicAdd(&g_cursor[c.w], 1);
        g_src[p0] = r.x;
        g_src[p1] = r.y;
        g_src[p2] = r.z;
        g_src[p3] = r.w;
    }
}

// ---------------- fp16 mma GEMM: C[rows,128](fp16) = [row_scale .*] (A @ W) ----------------
#define AHS 136
#define BHS 136
#define SMEM_GEMM ((128 * AHS + 128 * BHS) * 2)

__device__ __forceinline__ void mma_f16(float* c, uint32_t a0, uint32_t a1, uint32_t a2,
                                        uint32_t a3, uint32_t b0, uint32_t b1) {
    asm volatile(
        "mma.sync.aligned.m16n8k16.row.col.f32.f16.f16.f32 "
        "{%0,%1,%2,%3}, {%4,%5,%6,%7}, {%8,%9}, {%0,%1,%2,%3};"
        : "+f"(c[0]), "+f"(c[1]), "+f"(c[2]), "+f"(c[3])
        : "r"(a0), "r"(a1), "r"(a2), "r"(a3), "r"(b0), "r"(b1));
}

__global__ void __launch_bounds__(256, 2) k_gemm_h(
    const void* __restrict__ Ain, int a_fp32,
    const float* __restrict__ W, __half* __restrict__ C,
    const float* __restrict__ row_scale, int M) {
    extern __shared__ __half sh[];
    __half* As = sh;
    __half* Bs = sh + 128 * AHS;
    int tid = threadIdx.x;
    int row0 = blockIdx.x * 128;

    if (a_fp32) {
        const float* A = (const float*)Ain;
        for (int i = tid; i < 4096; i += 256) {
            int r = i >> 5, c = (i & 31) << 2;
            int gr = row0 + r;
            float4 v = make_float4(0.f, 0.f, 0.f, 0.f);
            if (gr < M) v = *(const float4*)(A + (size_t)gr * 128 + c);
            uint2 u;
            u.x = h2u(__floats2half2_rn(v.x, v.y));
            u.y = h2u(__floats2half2_rn(v.z, v.w));
            *(uint2*)(As + r * AHS + c) = u;
        }
    } else {
        const __half* A = (const __half*)Ain;
        for (int i = tid; i < 4096; i += 256) {
            int r = i >> 5, c = (i & 31) << 2;
            int gr = row0 + r;
            uint2 u = make_uint2(0u, 0u);
            if (gr < M) u = *(const uint2*)(A + (size_t)gr * 128 + c);
            *(uint2*)(As + r * AHS + c) = u;
        }
    }

    for (int t = 0; t < 8; t++) {
        int idx = tid + t * 256;
        int k2 = (idx & 31) | (((idx >> 5) & 1) << 5);
        int n4 = (idx >> 6) << 2;
        int k = k2 * 2;
        const float* w0 = W + (size_t)k * 128 + n4;
        float4 r0 = *(const float4*)w0;
        float4 r1 = *(const float4*)(w0 + 128);
        *(uint32_t*)(Bs + (n4 + 0) * BHS + k) = h2u(__floats2half2_rn(r0.x, r1.x));
        *(uint32_t*)(Bs + (n4 + 1) * BHS + k) = h2u(__floats2half2_rn(r0.y, r1.y));
        *(uint32_t*)(Bs + (n4 + 2) * BHS + k) = h2u(__floats2half2_rn(r0.z, r1.z));
        *(uint32_t*)(Bs + (n4 + 3) * BHS + k) = h2u(__floats2half2_rn(r0.w, r1.w));
    }
    __syncthreads();

    int wid = tid >> 5, lane = tid & 31;
    int wm = (wid >> 2) * 64;
    int wn = (wid & 3) * 32;
    int g = lane >> 2, tg = lane & 3;

    float acc[4][4][4];
#pragma unroll
    for (int mt = 0; mt < 4; mt++)
#pragma unroll
        for (int nt = 0; nt < 4; nt++)
#pragma unroll
            for (int r = 0; r < 4; r++) acc[mt][nt][r] = 0.f;

#pragma unroll
    for (int k0 = 0; k0 < 128; k0 += 16) {
        uint32_t af[4][4];
#pragma unroll
        for (int mt = 0; mt < 4; mt++) {
            const __half* ap = As + (wm + mt * 16) * AHS + k0 + tg * 2;
            af[mt][0] = *(const uint32_t*)(ap + g * AHS);
            af[mt][1] = *(const uint32_t*)(ap + (g + 8) * AHS);
            af[mt][2] = *(const uint32_t*)(ap + g * AHS + 8);
            af[mt][3] = *(const uint32_t*)(ap + (g + 8) * AHS + 8);
        }
        uint32_t bf[4][2];
#pragma unroll
        for (int nt = 0; nt < 4; nt++) {
            const __half* bp = Bs + (wn + nt * 8 + g) * BHS + k0 + tg * 2;
            bf[nt][0] = *(const uint32_t*)(bp);
            bf[nt][1] = *(const uint32_t*)(bp + 8);
        }
#pragma unroll
        for (int mt = 0; mt < 4; mt++)
#pragma unroll
            for (int nt = 0; nt < 4; nt++)
                mma_f16(acc[mt][nt], af[mt][0], af[mt][1], af[mt][2], af[mt][3],
                        bf[nt][0], bf[nt][1]);
    }

#pragma unroll
    for (int nt = 0; nt < 4; nt++) {
        int col = wn + nt * 8 + tg * 2;
#pragma unroll
        for (int mt = 0; mt < 4; mt++) {
            int r0 = row0 + wm + mt * 16 + g;
            if (r0 < M) {
                float s0 = row_scale ? row_scale[r0] : 1.0f;
                *(uint32_t*)(C + (size_t)r0 * 128 + col) =
                    h2u(__floats2half2_rn(acc[mt][nt][0] * s0, acc[mt][nt][1] * s0));
            }
            int r1 = r0 + 8;
            if (r1 < M) {
                float s1 = row_scale ? row_scale[r1] : 1.0f;
                *(uint32_t*)(C + (size_t)r1 * 128 + col) =
                    h2u(__floats2half2_rn(acc[mt][nt][2] * s1, acc[mt][nt][3] * s1));
            }
        }
    }
}

// ---------------- agg core: 4 output floats for (node, lane) ----------------
template <int PRESCALED>
__device__ __forceinline__ void agg_row(
    const __half* __restrict__ P, const float* __restrict__ bias,
    int node, int lane, float& ox, float& oy, float& oz, float& ow) {
    int c4 = lane * 4;
    float di = g_dinv[node];

    uint2 sv = *(const uint2*)(P + (size_t)node * FH + c4);
    float2 f0 = __half22float2(u2h(sv.x));
    float2 f1 = __half22float2(u2h(sv.y));
    float selfs = PRESCALED ? 1.0f : di;
    float ax = selfs * f0.x, ay = selfs * f0.y, az = selfs * f1.x, aw = selfs * f1.y;

    int beg = g_ptr[node], end = g_ptr[node + 1];
    int j = beg;
    for (; j + 8 <= end; j += 8) {
        int s[8];
#pragma unroll
        for (int q = 0; q < 8; q++) s[q] = g_src[j + q];
        float d[8];
#pragma unroll
        for (int q = 0; q < 8; q++) d[q] = PRESCALED ? 1.0f : g_dinv[s[q]];
        uint2 v[8];
#pragma unroll
        for (int q = 0; q < 8; q++) v[q] = *(const uint2*)(P + (size_t)s[q] * FH + c4);
#pragma unroll
        for (int q = 0; q < 8; q++) {
            float2 a = __half22float2(u2h(v[q].x));
            float2 b = __half22float2(u2h(v[q].y));
            if (PRESCALED) {
                ax += a.x; ay += a.y; az += b.x; aw += b.y;
            } else {
                ax = fmaf(d[q], a.x, ax); ay = fmaf(d[q], a.y, ay);
                az = fmaf(d[q], b.x, az); aw = fmaf(d[q], b.y, aw);
            }
        }
    }
    for (; j + 4 <= end; j += 4) {
        int s[4];
#pragma unroll
        for (int q = 0; q < 4; q++) s[q] = g_src[j + q];
        float d[4];
#pragma unroll
        for (int q = 0; q < 4; q++) d[q] = PRESCALED ? 1.0f : g_dinv[s[q]];
        uint2 v[4];
#pragma unroll
        for (int q = 0; q < 4; q++) v[q] = *(const uint2*)(P + (size_t)s[q] * FH + c4);
#pragma unroll
        for (int q = 0; q < 4; q++) {
            float2 a = __half22float2(u2h(v[q].x));
            float2 b = __half22float2(u2h(v[q].y));
            if (PRESCALED) {
                ax += a.x; ay += a.y; az += b.x; aw += b.y;
            } else {
                ax = fmaf(d[q], a.x, ax); ay = fmaf(d[q], a.y, ay);
                az = fmaf(d[q], b.x, az); aw = fmaf(d[q], b.y, aw);
            }
        }
    }
    for (; j < end; j++) {
        int s0 = g_src[j];
        float d0 = PRESCALED ? 1.0f : g_dinv[s0];
        uint2 v0 = *(const uint2*)(P + (size_t)s0 * FH + c4);
        float2 a0 = __half22float2(u2h(v0.x)), b0 = __half22float2(u2h(v0.y));
        ax = fmaf(d0, a0.x, ax); ay = fmaf(d0, a0.y, ay);
        az = fmaf(d0, b0.x, az); aw = fmaf(d0, b0.y, aw);
    }

    float4 bb = *(const float4*)(bias + c4);
    ox = fmaxf(fmaf(ax, di, bb.x), 0.f);
    oy = fmaxf(fmaf(ay, di, bb.y), 0.f);
    oz = fmaxf(fmaf(az, di, bb.z), 0.f);
    ow = fmaxf(fmaf(aw, di, bb.w), 0.f);
}

// layer-1 agg: h1 -> fp16 buffer (unchanged)
__global__ void __launch_bounds__(256) k_agg_h1(
    const __half* __restrict__ P, __half* __restrict__ Hout,
    const float* __restrict__ bias) {
    int node = (blockIdx.x * blockDim.x + threadIdx.x) >> 5;
    int lane = threadIdx.x & 31;
    if (node >= NN) return;
    float ox, oy, oz, ow;
    agg_row<0>(P, bias, node, lane, ox, oy, oz, ow);
    uint2 o;
    o.x = h2u(__floats2half2_rn(ox, oy));
    o.y = h2u(__floats2half2_rn(oz, ow));
    *(uint2*)(Hout + (size_t)node * FH + lane * 4) = o;
}

// layer-2 agg fused with BLOCK-STAGED pooled accumulation.
// 8 warps = 8 consecutive nodes (batch sorted -> <=2 distinct gids typical).
// Warps stage h2 rows in smem; leader warp per distinct gid sums matching
// warps and issues ONE set of global atomics -> 8x fewer RMWs than R13.
__global__ void __launch_bounds__(256) k_agg_pool2(
    const __half* __restrict__ P, const float* __restrict__ bias,
    const int* __restrict__ batch) {
    __shared__ float sbuf[8][FH];
    __shared__ int sgid[8];
    int warp = threadIdx.x >> 5;
    int lane = threadIdx.x & 31;
    int node = blockIdx.x * 8 + warp;   // NN=40000, grid=5000 -> all blocks full

    float ox, oy, oz, ow;
    agg_row<1>(P, bias, node, lane, ox, oy, oz, ow);

    int gid = batch[node];
    if (lane == 0) sgid[warp] = gid;
    float4 mine = make_float4(ox, oy, oz, ow);
    *(float4*)&sbuf[warp][lane * 4] = mine;
    __syncthreads();

    // leader = lowest warp index holding this gid
    bool leader = true;
#pragma unroll
    for (int k = 0; k < 8; k++)
        if (k < warp && sgid[k] == gid) leader = false;

    if (leader) {
        float4 acc = mine;
#pragma unroll
        for (int k = 0; k < 8; k++) {
            if (k > warp && sgid[k] == gid) {
                float4 v = *(const float4*)&sbuf[k][lane * 4];
                acc.x += v.x; acc.y += v.y; acc.z += v.z; acc.w += v.w;
            }
        }
        float* dst = g_pool + gid * FH + lane * 4;
        atomicAdd(dst + 0, acc.x);
        atomicAdd(dst + 1, acc.y);
        atomicAdd(dst + 2, acc.z);
        atomicAdd(dst + 3, acc.w);
    }
}

// ---------------- FC + log_softmax over pooled sums (self-zeros g_pool) ----------------
__device__ __forceinline__ int lower_bound_i(const int* __restrict__ b, int n, int key) {
    int lo = 0, hi = n;
    while (lo < hi) {
        int mid = (lo + hi) >> 1;
        if (b[mid] < key) lo = mid + 1; else hi = mid;
    }
    return lo;
}

__global__ void __launch_bounds__(128) k_fc(
    const int* __restrict__ batch,
    const float* __restrict__ Wfc, const float* __restrict__ bfc,
    float* __restrict__ out) {
    int g = blockIdx.x;
    int tid = threadIdx.x;
    __shared__ float pooled[FH];
    __shared__ float logit[NOUT];
    __shared__ int range[2];

    if (tid == 0) {
        range[0] = lower_bound_i(batch, NN, g);
        range[1] = lower_bound_i(batch, NN, g + 1);
    }
    __syncthreads();
    float cnt = fmaxf((float)(range[1] - range[0]), 1.0f);
    float pv = g_pool[g * FH + tid];
    g_pool[g * FH + tid] = 0.0f;   // self-zero for the next call
    pooled[tid] = pv / cnt;
    __syncthreads();

    if (tid < NOUT) {
        float acc = bfc[tid];
        for (int k = 0; k < FH; k++) acc = fmaf(pooled[k], Wfc[k * NOUT + tid], acc);
        logit[tid] = acc;
    }
    __syncthreads();

    if (tid == 0) {
        float m = -1e30f;
        for (int o = 0; o < NOUT; o++) m = fmaxf(m, logit[o]);
        float se = 0.f;
        for (int o = 0; o < NOUT; o++) se += expf(logit[o] - m);
        float lse = m + logf(se);
        for (int o = 0; o < NOUT; o++) out[g * NOUT + o] = logit[o] - lse;
    }
}

// ---------------- launch (R16 schedule; agg2+pool fused) ----------------
struct HxRes {
    cudaStream_t s2;
    cudaEvent_t e0, e1;
    HxRes() {
        cudaStreamCreateWithFlags(&s2, cudaStreamNonBlocking);
        cudaEventCreateWithFlags(&e0, cudaEventDisableTiming);
        cudaEventCreateWithFlags(&e1, cudaEventDisableTiming);
    }
};

extern "C" void kernel_launch(void* const* d_in, const int* in_sizes, int n_in,
                              void* d_out, int out_size) {
    static HxRes hx;

    const float* x    = (const float*)d_in[0];
    const int*   ei   = (const int*)d_in[1];
    const int*   batc = (const int*)d_in[2];
    const float* W1   = (const float*)d_in[3];
    const float* b1   = (const float*)d_in[4];
    const float* W2   = (const float*)d_in[5];
    const float* b2   = (const float*)d_in[6];
    const float* Wfc  = (const float*)d_in[7];
    const float* bfc  = (const float*)d_in[8];
    float* out = (float*)d_out;

    void *p0, *p1;
    cudaGetSymbolAddress(&p0, g_buf0);
    cudaGetSymbolAddress(&p1, g_buf1);
    __half* bufP1 = (__half*)p0;                     // P1 = X @ W1
    __half* bufP2 = (__half*)p0 + (size_t)NN * FH;   // P2 = dinv .* (H1 @ W2)
    __half* bufH  = (__half*)p1;                     // H1

    float* dinv_ptr;
    cudaGetSymbolAddress((void**)&dinv_ptr, g_dinv);

    cudaFuncSetAttribute(k_gemm_h,
                         cudaFuncAttributeMaxDynamicSharedMemorySize, SMEM_GEMM);

    int gblocks = (NN + 127) / 128;

    // fork: GEMM1 (P1 = X @ W1) at t=0, concurrent with the whole CSR build
    cudaEventRecord(hx.e0, 0);
    cudaStreamWaitEvent(hx.s2, hx.e0, 0);
    k_gemm_h<<<gblocks, 256, SMEM_GEMM, hx.s2>>>(x, 1, W1, bufP1, nullptr, NN);
    cudaEventRecord(hx.e1, hx.s2);

    // CSR build on the main (capturing) stream — counts pre-zeroed (self-zeroing)
    k_hist<<<(EE / 4 + 255) / 256, 256>>>(ei);
    k_block_reduce<<<NBLK, 256>>>();
    k_ptr_dinv<<<NBLK, 256>>>();
    k_scatter<<<(EE / 4 + 255) / 256, 256>>>(ei);

    // join GEMM1, then h1 = relu(agg(P1) + b1)  (dinv gathered per edge)
    cudaStreamWaitEvent(0, hx.e1, 0);
    k_agg_h1<<<NN / 8, 256>>>(bufP1, bufH, b1);

    // layer 2: P2 = dinv .* (H1 @ W2); agg2 fused with block-staged pooling
    k_gemm_h<<<gblocks, 256, SMEM_GEMM>>>(bufH, 0, W2, bufP2, dinv_ptr, NN);
    k_agg_pool2<<<NN / 8, 256>>>(bufP2, b2, batc);

    // FC + log_softmax over pooled sums (self-zeros g_pool)
    k_fc<<<GG, 128>>>(batc, Wfc, bfc, out);
}